// round 1
// baseline (speedup 1.0000x reference)
#include <cuda_runtime.h>
#include <cstdint>

#define EMBED 1024
#define HEADS 16
#define HDIM  64
#define LSEQ  1024
#define MAXB  4

// ---------------- scratch (device globals; no allocations allowed) ----------------
__device__ float g_WqE[EMBED * HEADS];          // effective Wq·w1  [e][n]
__device__ float g_WkE[EMBED * HEADS];          // effective Wk·w2  [e][n]
__device__ float g_bqE[HEADS];
__device__ float g_Aexp[MAXB * HEADS * LSEQ];   // exp(2*sq) laid out [b][n][i]
__device__ float g_Bexp[MAXB * HEADS * LSEQ];   // exp(2*sk) laid out [b][n][j]
__device__ float g_vh[(size_t)MAXB * HEADS * LSEQ * HDIM];  // [b][n][j][d]
__device__ float g_att[(size_t)MAXB * LSEQ * EMBED];        // attention output, token-major

// ---------------- K0: effective weights --------------------------------------------
// WqE[e][n] = sum_d Wq[e][n*64+d] * w1[d]; same for K with w2; plus bqE.
__global__ void k_weff(const float* __restrict__ Wq, const float* __restrict__ Wk,
                       const float* __restrict__ bq, const float* __restrict__ aw) {
    int t = blockIdx.x * blockDim.x + threadIdx.x;   // 0..32767
    int side = t >> 14;                               // 0 = q, 1 = k
    int u = t & 16383;
    int e = u >> 4, n = u & 15;
    const float* W = side ? Wk : Wq;
    const float* w = aw + side * HDIM;
    float s = 0.f;
#pragma unroll 8
    for (int d = 0; d < HDIM; d++)
        s += W[(size_t)e * (HEADS * HDIM) + n * HDIM + d] * w[d];
    if (side) g_WkE[e * 16 + n] = s;
    else      g_WqE[e * 16 + n] = s;
    if (!side && e == 0) {
        float sb = 0.f;
#pragma unroll 8
        for (int d = 0; d < HDIM; d++) sb += bq[n * HDIM + d] * w[d];
        g_bqE[n] = sb;
    }
}

// ---------------- K1: sq/sk = x @ WE (+bqE), then exp(2*s) -------------------------
// grid: (B*L/16, 2), 256 threads, 64KB dynamic smem holding WE
__global__ void __launch_bounds__(256) k_sqk(const float* __restrict__ qin,
                                             const float* __restrict__ kin) {
    extern __shared__ float sWE[];                    // [1024][16]
    int side = blockIdx.y;
    const float* WE = side ? g_WkE : g_WqE;
    int tid = threadIdx.x;
    {
        const float4* src = (const float4*)WE;
        float4* dst = (float4*)sWE;
        for (int t = tid; t < (EMBED * HEADS) / 4; t += 256) dst[t] = src[t];
    }
    __syncthreads();

    int n  = tid & 15;
    int rl = tid >> 4;                                 // 0..15
    int row = blockIdx.x * 16 + rl;                    // 0..B*L-1
    const float* xr = (side ? kin : qin) + (size_t)row * EMBED;

    float s0 = 0.f, s1 = 0.f, s2 = 0.f, s3 = 0.f;
#pragma unroll 4
    for (int e = 0; e < EMBED; e += 4) {
        float4 xv = *(const float4*)(xr + e);
        s0 += xv.x * sWE[(e + 0) * 16 + n];
        s1 += xv.y * sWE[(e + 1) * 16 + n];
        s2 += xv.z * sWE[(e + 2) * 16 + n];
        s3 += xv.w * sWE[(e + 3) * 16 + n];
    }
    float s = (s0 + s1) + (s2 + s3);
    if (!side) s += g_bqE[n];
    int b = row >> 10, i = row & 1023;
    float val = __expf(2.0f * s);
    float* dst = side ? g_Bexp : g_Aexp;
    dst[((b * HEADS + n) << 10) + i] = val;
}

// ---------------- K2/K4: SIMT fp32 GEMM  C[M,1024] = A[M,1024] @ W[1024,1024] ------
// MODE 0: C = A@W + bias, plain row-major into Cout.
// MODE 1: write into g_vh with [b][head][j][d] layout (head == blockIdx.x, BN==64).
template <int MODE>
__global__ void __launch_bounds__(256) k_gemm(const float* __restrict__ A,
                                              const float* __restrict__ W,
                                              const float* __restrict__ bias,
                                              float* __restrict__ Cout) {
    const int BM = 128, BN = 64, BK = 16;
    __shared__ float As[BK][BM];
    __shared__ float Bs[BK][BN];

    int tid = threadIdx.x;
    int tx = tid & 15;          // n-dir, 4 cols each
    int ty = tid >> 4;          // m-dir, 8 rows each
    int m0 = blockIdx.y * BM;
    int n0 = blockIdx.x * BN;

    float acc[8][4];
#pragma unroll
    for (int a = 0; a < 8; a++)
#pragma unroll
        for (int b = 0; b < 4; b++) acc[a][b] = 0.f;

    for (int kt = 0; kt < EMBED; kt += BK) {
        // A tile load: 128x16 -> As[k][m] (transposed)
#pragma unroll
        for (int s = 0; s < 2; s++) {
            int id = tid * 2 + s;          // 0..511
            int m = id >> 2;               // 0..127
            int kq = (id & 3) * 4;         // 0,4,8,12
            float4 av = *(const float4*)(A + (size_t)(m0 + m) * EMBED + kt + kq);
            As[kq + 0][m] = av.x;
            As[kq + 1][m] = av.y;
            As[kq + 2][m] = av.z;
            As[kq + 3][m] = av.w;
        }
        // B tile load: 16x64 direct
        {
            int kb = tid >> 4, nf = tid & 15;
            *(float4*)&Bs[kb][nf * 4] =
                *(const float4*)(W + (size_t)(kt + kb) * (HEADS * HDIM) + n0 + nf * 4);
        }
        __syncthreads();

#pragma unroll
        for (int kk = 0; kk < BK; kk++) {
            float af[8], bf[4];
            *(float4*)(af)     = *(const float4*)&As[kk][ty * 8];
            *(float4*)(af + 4) = *(const float4*)&As[kk][ty * 8 + 4];
            *(float4*)(bf)     = *(const float4*)&Bs[kk][tx * 4];
#pragma unroll
            for (int mi = 0; mi < 8; mi++)
#pragma unroll
                for (int nj = 0; nj < 4; nj++)
                    acc[mi][nj] += af[mi] * bf[nj];
        }
        __syncthreads();
    }

    if (MODE == 0) {
        int col = n0 + tx * 4;
        float4 bv = *(const float4*)(bias + col);
#pragma unroll
        for (int mi = 0; mi < 8; mi++) {
            int row = m0 + ty * 8 + mi;
            float4 o;
            o.x = acc[mi][0] + bv.x;
            o.y = acc[mi][1] + bv.y;
            o.z = acc[mi][2] + bv.z;
            o.w = acc[mi][3] + bv.w;
            *(float4*)(Cout + (size_t)row * (HEADS * HDIM) + col) = o;
        }
    } else {
        int head = blockIdx.x;   // BN==64 tiles align with heads
#pragma unroll
        for (int mi = 0; mi < 8; mi++) {
            int row = m0 + ty * 8 + mi;
            int b = row >> 10, j = row & 1023;
            float* dst = g_vh + ((((size_t)(b * HEADS + head)) << 10) + j) * HDIM + tx * 4;
            float4 o;
            o.x = acc[mi][0]; o.y = acc[mi][1]; o.z = acc[mi][2]; o.w = acc[mi][3];
            *(float4*)dst = o;
        }
    }
}

// ---------------- K3: attention core -----------------------------------------------
// p_ij = exp( (u-1)/(u+1) ), u = a_i*b_j = e^{2(sq_i+sk_j)}; out_i = (sum_j p v_j)/sum_j p
// grid (L/128, HEADS, B), 256 threads. Thread owns one query row, half of HDIM.
__global__ void __launch_bounds__(256) k_attn() {
    __shared__ float sv[128 * HDIM];   // V tile  [j][d]  32KB
    __shared__ float sb[128];          // b_j tile

    int b = blockIdx.z, n = blockIdx.y;
    int i0 = blockIdx.x * 128;
    int tid = threadIdx.x;
    int il = tid & 127;
    int dh = tid >> 7;                 // 0/1 -> d in [dh*32, dh*32+32)
    int i = i0 + il;

    const float* Aex = g_Aexp + ((b * HEADS + n) << 10);
    const float* Bex = g_Bexp + ((b * HEADS + n) << 10);
    const float* V   = g_vh + (((size_t)(b * HEADS + n)) << 10) * HDIM;

    float a = Aex[i];
    float acc[32];
#pragma unroll
    for (int c = 0; c < 32; c++) acc[c] = 0.f;
    float rsum = 0.f;

    for (int jt = 0; jt < LSEQ; jt += 128) {
        // cooperative loads
        {
            const float4* gsrc = (const float4*)(V + (size_t)jt * HDIM);
            float4* sdst = (float4*)sv;
#pragma unroll
            for (int qd = 0; qd < 8; qd++) sdst[tid + qd * 256] = gsrc[tid + qd * 256];
            if (tid < 128) sb[tid] = Bex[jt + tid];
        }
        __syncthreads();

#pragma unroll 4
        for (int jj = 0; jj < 128; jj++) {
            float bj = sb[jj];
            float u = a * bj;
            float r;
            asm("rcp.approx.f32 %0, %1;" : "=f"(r) : "f"(u + 1.0f));
            float p = __expf((u - 1.0f) * r);
            rsum += p;
            const float4* vp = (const float4*)(sv + jj * HDIM + dh * 32);
#pragma unroll
            for (int qd = 0; qd < 8; qd++) {
                float4 vv = vp[qd];
                acc[qd * 4 + 0] += p * vv.x;
                acc[qd * 4 + 1] += p * vv.y;
                acc[qd * 4 + 2] += p * vv.z;
                acc[qd * 4 + 3] += p * vv.w;
            }
        }
        __syncthreads();
    }

    float inv = 1.0f / rsum;
    float* outp = g_att + (size_t)(b * LSEQ + i) * (HEADS * HDIM) + n * HDIM + dh * 32;
#pragma unroll
    for (int qd = 0; qd < 8; qd++) {
        float4 o;
        o.x = acc[qd * 4 + 0] * inv;
        o.y = acc[qd * 4 + 1] * inv;
        o.z = acc[qd * 4 + 2] * inv;
        o.w = acc[qd * 4 + 3] * inv;
        *(float4*)(outp + qd * 4) = o;
    }
}

// ---------------- K5: layernorm (in-place on d_out rows) ---------------------------
__global__ void __launch_bounds__(256) k_ln(float* __restrict__ y,
                                            const float* __restrict__ gamma,
                                            const float* __restrict__ beta) {
    int row = blockIdx.x, tid = threadIdx.x;
    float4* yp = (float4*)(y + (size_t)row * 1024);
    float4 v = yp[tid];
    float s  = v.x + v.y + v.z + v.w;
    float ss = v.x * v.x + v.y * v.y + v.z * v.z + v.w * v.w;

    __shared__ float red[16];
    int lane = tid & 31, wid = tid >> 5;
#pragma unroll
    for (int o = 16; o; o >>= 1) {
        s  += __shfl_xor_sync(0xffffffffu, s,  o);
        ss += __shfl_xor_sync(0xffffffffu, ss, o);
    }
    if (lane == 0) { red[wid] = s; red[wid + 8] = ss; }
    __syncthreads();
    if (tid == 0) {
        float S = 0.f, SS = 0.f;
        for (int w = 0; w < 8; w++) { S += red[w]; SS += red[w + 8]; }
        red[0] = S; red[1] = SS;
    }
    __syncthreads();
    float mean = red[0] * (1.0f / 1024.0f);
    float var  = red[1] * (1.0f / 1024.0f) - mean * mean;
    float rr = rsqrtf(var + 1e-6f);

    float4 g  = ((const float4*)gamma)[tid];
    float4 bb = ((const float4*)beta)[tid];
    float4 o;
    o.x = (v.x - mean) * rr * g.x + bb.x;
    o.y = (v.y - mean) * rr * g.y + bb.y;
    o.z = (v.z - mean) * rr * g.z + bb.z;
    o.w = (v.w - mean) * rr * g.w + bb.w;
    yp[tid] = o;
}

// ---------------- launcher ----------------------------------------------------------
extern "C" void kernel_launch(void* const* d_in, const int* in_sizes, int n_in,
                              void* d_out, int out_size) {
    (void)n_in; (void)out_size;
    const float* k_in  = (const float*)d_in[0];
    const float* q_in  = (const float*)d_in[1];
    const float* v_in  = (const float*)d_in[2];
    const float* Wq    = (const float*)d_in[3];
    const float* bq    = (const float*)d_in[4];
    const float* Wk    = (const float*)d_in[5];
    const float* Wv    = (const float*)d_in[6];
    const float* Wp    = (const float*)d_in[7];
    const float* bp    = (const float*)d_in[8];
    const float* aw    = (const float*)d_in[9];
    const float* gamma = (const float*)d_in[10];
    const float* beta  = (const float*)d_in[11];
    float* out = (float*)d_out;

    int B = in_sizes[0] / (LSEQ * EMBED);   // 4
    int M = B * LSEQ;                        // 4096

    float* p_att = nullptr;
    cudaGetSymbolAddress((void**)&p_att, g_att);

    cudaFuncSetAttribute(k_sqk, cudaFuncAttributeMaxDynamicSharedMemorySize, 65536);

    // K0: effective q/k weights (tiny)
    k_weff<<<128, 256>>>(Wq, Wk, bq, aw);
    // K1: sq/sk + exp
    k_sqk<<<dim3(M / 16, 2), 256, 65536>>>(q_in, k_in);
    // K2: V projection into per-head layout
    k_gemm<1><<<dim3((HEADS * HDIM) / 64, M / 128), 256>>>(v_in, Wv, nullptr, nullptr);
    // K3: attention
    k_attn<<<dim3(LSEQ / 128, HEADS, B), 256>>>();
    // K4: output projection (+bias) into d_out
    k_gemm<0><<<dim3((HEADS * HDIM) / 64, M / 128), 256>>>(p_att, Wp, bp, out);
    // K5: layernorm in place
    k_ln<<<M, 256>>>(out, gamma, beta);
}

// round 3
// speedup vs baseline: 1.1048x; 1.1048x over previous
#include <cuda_runtime.h>
#include <cstdint>

#define EMBED 1024
#define HEADS 16
#define HDIM  64
#define LSEQ  1024
#define MAXB  4

typedef unsigned long long u64;

// ---------------- packed f32x2 helpers (Blackwell FFMA2) ---------------------------
__device__ __forceinline__ u64 fma2(u64 a, u64 b, u64 c) {
    u64 d;
    asm("fma.rn.f32x2 %0, %1, %2, %3;" : "=l"(d) : "l"(a), "l"(b), "l"(c));
    return d;
}
__device__ __forceinline__ u64 dup2(float x) {
    u64 d;
    unsigned u = __float_as_uint(x);
    asm("mov.b64 %0, {%1, %1};" : "=l"(d) : "r"(u));
    return d;
}
union F4U2 { float4 f4; u64 u2[2]; float f[4]; };

// ---------------- scratch (device globals; no allocations allowed) ----------------
__device__ float g_WqE[EMBED * HEADS];
__device__ float g_WkE[EMBED * HEADS];
__device__ float g_bqE[HEADS];
__device__ float g_Aexp[MAXB * HEADS * LSEQ];   // exp(2*sq)  [b][n][i]
__device__ float g_Bexp[MAXB * HEADS * LSEQ];   // exp(2*sk)  [b][n][j]
__device__ float g_vh[(size_t)MAXB * HEADS * LSEQ * HDIM];  // [b][n][j][d]
__device__ float g_att[(size_t)MAXB * LSEQ * EMBED];        // token-major attn out

// ---------------- K0: effective weights --------------------------------------------
__global__ void k_weff(const float* __restrict__ Wq, const float* __restrict__ Wk,
                       const float* __restrict__ bq, const float* __restrict__ aw) {
    int t = blockIdx.x * blockDim.x + threadIdx.x;
    int side = t >> 14;
    int u = t & 16383;
    int e = u >> 4, n = u & 15;
    const float* W = side ? Wk : Wq;
    const float* w = aw + side * HDIM;
    float s = 0.f;
#pragma unroll 8
    for (int d = 0; d < HDIM; d++)
        s += W[(size_t)e * (HEADS * HDIM) + n * HDIM + d] * w[d];
    if (side) g_WkE[e * 16 + n] = s;
    else      g_WqE[e * 16 + n] = s;
    if (!side && e == 0) {
        float sb = 0.f;
#pragma unroll 8
        for (int d = 0; d < HDIM; d++) sb += bq[n * HDIM + d] * w[d];
        g_bqE[n] = sb;
    }
}

// ---------------- K1: sq/sk = x @ WE (+bqE), then exp(2*s) -------------------------
__global__ void __launch_bounds__(256) k_sqk(const float* __restrict__ qin,
                                             const float* __restrict__ kin) {
    extern __shared__ float sWE[];                    // [1024][16]
    int side = blockIdx.y;
    const float* WE = side ? g_WkE : g_WqE;
    int tid = threadIdx.x;
    {
        const float4* src = (const float4*)WE;
        float4* dst = (float4*)sWE;
        for (int t = tid; t < (EMBED * HEADS) / 4; t += 256) dst[t] = src[t];
    }
    __syncthreads();

    int n  = tid & 15;
    int rl = tid >> 4;
    int row = blockIdx.x * 16 + rl;
    const float* xr = (side ? kin : qin) + (size_t)row * EMBED;

    float s0 = 0.f, s1 = 0.f, s2 = 0.f, s3 = 0.f;
#pragma unroll 4
    for (int e = 0; e < EMBED; e += 4) {
        float4 xv = *(const float4*)(xr + e);
        s0 += xv.x * sWE[(e + 0) * 16 + n];
        s1 += xv.y * sWE[(e + 1) * 16 + n];
        s2 += xv.z * sWE[(e + 2) * 16 + n];
        s3 += xv.w * sWE[(e + 3) * 16 + n];
    }
    float s = (s0 + s1) + (s2 + s3);
    if (!side) s += g_bqE[n];
    int b = row >> 10, i = row & 1023;
    float val = __expf(2.0f * s);
    float* dst = side ? g_Bexp : g_Aexp;
    dst[((b * HEADS + n) << 10) + i] = val;
}

// ---------------- K2/K4: FFMA2 GEMM  C[M,1024] = A[M,1024] @ W[1024,1024] ----------
// BM=128, BN=128, BK=16, 256 threads, 8x8 microtile via packed f32x2.
// MODE 0: C = A@W + bias. MODE 1: scatter into g_vh [b][head][j][d].
template <int MODE>
__global__ void __launch_bounds__(256, 2) k_gemm(const float* __restrict__ A,
                                                 const float* __restrict__ W,
                                                 const float* __restrict__ bias,
                                                 float* __restrict__ Cout) {
    const int BM = 128, BN = 128, BK = 16;
    __shared__ float As[BK][BM];   // transposed A tile
    __shared__ float Bs[BK][BN];

    int tid = threadIdx.x;
    int tx = tid & 15;             // n-dir: 8 cols (4 f32x2 pairs)
    int ty = tid >> 4;             // m-dir: 8 rows
    int m0 = blockIdx.y * BM;
    int n0 = blockIdx.x * BN;

    u64 acc[8][4];
#pragma unroll
    for (int a = 0; a < 8; a++)
#pragma unroll
        for (int b = 0; b < 4; b++) acc[a][b] = 0ull;

    for (int kt = 0; kt < EMBED; kt += BK) {
        // A tile: 128x16 -> As[k][m]
#pragma unroll
        for (int s = 0; s < 2; s++) {
            int id = tid * 2 + s;          // 0..511
            int m = id >> 2;
            int kq = (id & 3) * 4;
            float4 av = *(const float4*)(A + (size_t)(m0 + m) * EMBED + kt + kq);
            As[kq + 0][m] = av.x;
            As[kq + 1][m] = av.y;
            As[kq + 2][m] = av.z;
            As[kq + 3][m] = av.w;
        }
        // B tile: 16x128
#pragma unroll
        for (int s = 0; s < 2; s++) {
            int id = tid * 2 + s;          // 0..511
            int kb = id >> 5;              // 0..15
            int nf = id & 31;              // 0..31 (x4 floats)
            *(float4*)&Bs[kb][nf * 4] =
                *(const float4*)(W + (size_t)(kt + kb) * (HEADS * HDIM) + n0 + nf * 4);
        }
        __syncthreads();

#pragma unroll
        for (int kk = 0; kk < BK; kk++) {
            F4U2 a0, a1, b0, b1;
            a0.f4 = *(const float4*)&As[kk][ty * 8];
            a1.f4 = *(const float4*)&As[kk][ty * 8 + 4];
            b0.f4 = *(const float4*)&Bs[kk][tx * 8];
            b1.f4 = *(const float4*)&Bs[kk][tx * 8 + 4];
            u64 bp[4] = { b0.u2[0], b0.u2[1], b1.u2[0], b1.u2[1] };
            u64 ad[8];
#pragma unroll
            for (int mi = 0; mi < 4; mi++) { ad[mi] = dup2(a0.f[mi]); ad[mi + 4] = dup2(a1.f[mi]); }
#pragma unroll
            for (int mi = 0; mi < 8; mi++)
#pragma unroll
                for (int nj = 0; nj < 4; nj++)
                    acc[mi][nj] = fma2(ad[mi], bp[nj], acc[mi][nj]);
        }
        __syncthreads();
    }

    if (MODE == 0) {
        int col = n0 + tx * 8;
        F4U2 bv0, bv1;
        bv0.f4 = *(const float4*)(bias + col);
        bv1.f4 = *(const float4*)(bias + col + 4);
#pragma unroll
        for (int mi = 0; mi < 8; mi++) {
            int row = m0 + ty * 8 + mi;
            F4U2 o0, o1;
            o0.u2[0] = acc[mi][0]; o0.u2[1] = acc[mi][1];
            o1.u2[0] = acc[mi][2]; o1.u2[1] = acc[mi][3];
#pragma unroll
            for (int c = 0; c < 4; c++) { o0.f[c] += bv0.f[c]; o1.f[c] += bv1.f[c]; }
            *(float4*)(Cout + (size_t)row * (HEADS * HDIM) + col)     = o0.f4;
            *(float4*)(Cout + (size_t)row * (HEADS * HDIM) + col + 4) = o1.f4;
        }
    } else {
        int col = n0 + tx * 8;
        int head = col >> 6;
        int d = col & 63;
#pragma unroll
        for (int mi = 0; mi < 8; mi++) {
            int row = m0 + ty * 8 + mi;
            int b = row >> 10, j = row & 1023;
            float* dst = g_vh + ((((size_t)(b * HEADS + head)) << 10) + j) * HDIM + d;
            F4U2 o0, o1;
            o0.u2[0] = acc[mi][0]; o0.u2[1] = acc[mi][1];
            o1.u2[0] = acc[mi][2]; o1.u2[1] = acc[mi][3];
            *(float4*)(dst)     = o0.f4;
            *(float4*)(dst + 4) = o1.f4;
        }
    }
}

// ---------------- K3: attention core (2 queries/thread, FFMA2) ---------------------
// p_ij = exp((u-1)/(u+1)), u = a_i*b_j; out_i = (sum_j p v_j)/sum_j p
// grid (L/256, HEADS, B), 256 threads. Thread owns queries {i, i+128}, half of HDIM.
__global__ void __launch_bounds__(256, 2) k_attn() {
    __shared__ float sv[128 * HDIM];   // V tile [j][d], 32KB
    __shared__ float sb[128];

    int b = blockIdx.z, n = blockIdx.y;
    int i0 = blockIdx.x * 256;
    int tid = threadIdx.x;
    int il = tid & 127;
    int dh = tid >> 7;                 // d in [dh*32, dh*32+32)
    int iA = i0 + il;
    int iB = i0 + il + 128;

    const float* Aex = g_Aexp + ((b * HEADS + n) << 10);
    const float* Bex = g_Bexp + ((b * HEADS + n) << 10);
    const float* V   = g_vh + (((size_t)(b * HEADS + n)) << 10) * HDIM;

    float aA = Aex[iA];
    float aB = Aex[iB];
    u64 accA[16], accB[16];
#pragma unroll
    for (int c = 0; c < 16; c++) { accA[c] = 0ull; accB[c] = 0ull; }
    float rsA = 0.f, rsB = 0.f;

    for (int jt = 0; jt < LSEQ; jt += 128) {
        {
            const float4* gsrc = (const float4*)(V + (size_t)jt * HDIM);
            float4* sdst = (float4*)sv;
#pragma unroll
            for (int qd = 0; qd < 8; qd++) sdst[tid + qd * 256] = gsrc[tid + qd * 256];
            if (tid < 128) sb[tid] = Bex[jt + tid];
        }
        __syncthreads();

#pragma unroll 2
        for (int jj = 0; jj < 128; jj++) {
            float bj = sb[jj];
            float uA = aA * bj;
            float uB = aB * bj;
            float rA, rB;
            asm("rcp.approx.f32 %0, %1;" : "=f"(rA) : "f"(uA + 1.0f));
            asm("rcp.approx.f32 %0, %1;" : "=f"(rB) : "f"(uB + 1.0f));
            float pA = __expf((uA - 1.0f) * rA);
            float pB = __expf((uB - 1.0f) * rB);
            rsA += pA;
            rsB += pB;
            u64 pA2 = dup2(pA), pB2 = dup2(pB);
            const float4* vp = (const float4*)(sv + jj * HDIM + dh * 32);
#pragma unroll
            for (int qd = 0; qd < 8; qd++) {
                F4U2 vv; vv.f4 = vp[qd];
                accA[qd * 2 + 0] = fma2(pA2, vv.u2[0], accA[qd * 2 + 0]);
                accA[qd * 2 + 1] = fma2(pA2, vv.u2[1], accA[qd * 2 + 1]);
                accB[qd * 2 + 0] = fma2(pB2, vv.u2[0], accB[qd * 2 + 0]);
                accB[qd * 2 + 1] = fma2(pB2, vv.u2[1], accB[qd * 2 + 1]);
            }
        }
        __syncthreads();
    }

    float invA = 1.0f / rsA;
    float invB = 1.0f / rsB;
    float* outA = g_att + (size_t)(b * LSEQ + iA) * (HEADS * HDIM) + n * HDIM + dh * 32;
    float* outB = g_att + (size_t)(b * LSEQ + iB) * (HEADS * HDIM) + n * HDIM + dh * 32;
#pragma unroll
    for (int qd = 0; qd < 8; qd++) {
        F4U2 oA, oB;
        oA.u2[0] = accA[qd * 2]; oA.u2[1] = accA[qd * 2 + 1];
        oB.u2[0] = accB[qd * 2]; oB.u2[1] = accB[qd * 2 + 1];
#pragma unroll
        for (int c = 0; c < 4; c++) { oA.f[c] *= invA; oB.f[c] *= invB; }
        *(float4*)(outA + qd * 4) = oA.f4;
        *(float4*)(outB + qd * 4) = oB.f4;
    }
}

// ---------------- K5: layernorm ----------------------------------------------------
__global__ void __launch_bounds__(256) k_ln(float* __restrict__ y,
                                            const float* __restrict__ gamma,
                                            const float* __restrict__ beta) {
    int row = blockIdx.x, tid = threadIdx.x;
    float4* yp = (float4*)(y + (size_t)row * 1024);
    float4 v = yp[tid];
    float s  = v.x + v.y + v.z + v.w;
    float ss = v.x * v.x + v.y * v.y + v.z * v.z + v.w * v.w;

    __shared__ float red[16];
    int lane = tid & 31, wid = tid >> 5;
#pragma unroll
    for (int o = 16; o; o >>= 1) {
        s  += __shfl_xor_sync(0xffffffffu, s,  o);
        ss += __shfl_xor_sync(0xffffffffu, ss, o);
    }
    if (lane == 0) { red[wid] = s; red[wid + 8] = ss; }
    __syncthreads();
    if (tid == 0) {
        float S = 0.f, SS = 0.f;
        for (int w = 0; w < 8; w++) { S += red[w]; SS += red[w + 8]; }
        red[0] = S; red[1] = SS;
    }
    __syncthreads();
    float mean = red[0] * (1.0f / 1024.0f);
    float var  = red[1] * (1.0f / 1024.0f) - mean * mean;
    float rr = rsqrtf(var + 1e-6f);

    float4 g  = ((const float4*)gamma)[tid];
    float4 bb = ((const float4*)beta)[tid];
    float4 o;
    o.x = (v.x - mean) * rr * g.x + bb.x;
    o.y = (v.y - mean) * rr * g.y + bb.y;
    o.z = (v.z - mean) * rr * g.z + bb.z;
    o.w = (v.w - mean) * rr * g.w + bb.w;
    yp[tid] = o;
}

// ---------------- launcher ----------------------------------------------------------
extern "C" void kernel_launch(void* const* d_in, const int* in_sizes, int n_in,
                              void* d_out, int out_size) {
    (void)n_in; (void)out_size;
    const float* k_in  = (const float*)d_in[0];
    const float* q_in  = (const float*)d_in[1];
    const float* v_in  = (const float*)d_in[2];
    const float* Wq    = (const float*)d_in[3];
    const float* bq    = (const float*)d_in[4];
    const float* Wk    = (const float*)d_in[5];
    const float* Wv    = (const float*)d_in[6];
    const float* Wp    = (const float*)d_in[7];
    const float* bp    = (const float*)d_in[8];
    const float* aw    = (const float*)d_in[9];
    const float* gamma = (const float*)d_in[10];
    const float* beta  = (const float*)d_in[11];
    float* out = (float*)d_out;

    int B = in_sizes[0] / (LSEQ * EMBED);   // 4
    int M = B * LSEQ;                        // 4096

    float* p_att = nullptr;
    cudaGetSymbolAddress((void**)&p_att, g_att);

    cudaFuncSetAttribute(k_sqk, cudaFuncAttributeMaxDynamicSharedMemorySize, 65536);

    k_weff<<<128, 256>>>(Wq, Wk, bq, aw);
    k_sqk<<<dim3(M / 16, 2), 256, 65536>>>(q_in, k_in);
    // V projection: BM=128, BN=128
    k_gemm<1><<<dim3((HEADS * HDIM) / 128, M / 128), 256>>>(v_in, Wv, nullptr, nullptr);
    // attention: 256 queries per block
    k_attn<<<dim3(LSEQ / 256, HEADS, B), 256>>>();
    // output projection
    k_gemm<0><<<dim3(1024 / 128, M / 128), 256>>>(p_att, Wp, bp, out);
    k_ln<<<M, 256>>>(out, gamma, beta);
}

// round 4
// speedup vs baseline: 1.4963x; 1.3544x over previous
#include <cuda_runtime.h>
#include <cstdint>

#define EMBED 1024
#define HEADS 16
#define HDIM  64
#define LSEQ  1024
#define MAXB  4
#define MCH   32          // Chebyshev rank

typedef unsigned long long u64;

// ---------------- packed f32x2 helpers (Blackwell FFMA2) ---------------------------
__device__ __forceinline__ u64 fma2(u64 a, u64 b, u64 c) {
    u64 d;
    asm("fma.rn.f32x2 %0, %1, %2, %3;" : "=l"(d) : "l"(a), "l"(b), "l"(c));
    return d;
}
__device__ __forceinline__ u64 dup2(float x) {
    u64 d;
    unsigned u = __float_as_uint(x);
    asm("mov.b64 %0, {%1, %1};" : "=l"(d) : "r"(u));
    return d;
}
union F4U2 { float4 f4; u64 u2[2]; float f[4]; };

__device__ __forceinline__ float frcp(float x) {
    float r; asm("rcp.approx.f32 %0, %1;" : "=f"(r) : "f"(x)); return r;
}

// ---------------- scratch ----------------------------------------------------------
__device__ float g_WqE[EMBED * HEADS];
__device__ float g_WkE[EMBED * HEADS];
__device__ float g_bqE[HEADS];
__device__ float g_SQ[MAXB * HEADS * LSEQ];     // raw sq  [b][n][i]
__device__ float g_SK[MAXB * HEADS * LSEQ];     // raw sk  [b][n][j]
__device__ unsigned g_skmax_bits;
__device__ float g_ynodes[MCH];
__device__ float g_wbar[MCH];
__device__ float g_vh[(size_t)MAXB * HEADS * LSEQ * HDIM];  // [b][n][j][d]
__device__ float g_T[(size_t)MAXB * HEADS * MCH * HDIM];    // [bn][m][d]
__device__ float g_S[MAXB * HEADS * MCH];                    // [bn][m]
__device__ float g_att[(size_t)MAXB * LSEQ * EMBED];        // token-major attn out

// ---------------- K0: effective weights --------------------------------------------
__global__ void k_weff(const float* __restrict__ Wq, const float* __restrict__ Wk,
                       const float* __restrict__ bq, const float* __restrict__ aw) {
    int t = blockIdx.x * blockDim.x + threadIdx.x;
    if (t == 0) g_skmax_bits = 0u;
    int side = t >> 14;
    int u = t & 16383;
    int e = u >> 4, n = u & 15;
    const float* W = side ? Wk : Wq;
    const float* w = aw + side * HDIM;
    float s = 0.f;
#pragma unroll 8
    for (int d = 0; d < HDIM; d++)
        s += W[(size_t)e * (HEADS * HDIM) + n * HDIM + d] * w[d];
    if (side) g_WkE[e * 16 + n] = s;
    else      g_WqE[e * 16 + n] = s;
    if (!side && e == 0) {
        float sb = 0.f;
#pragma unroll 8
        for (int d = 0; d < HDIM; d++) sb += bq[n * HDIM + d] * w[d];
        g_bqE[n] = sb;
    }
}

// ---------------- K1: sq/sk = x @ WE (+bqE), store raw; track max|sk| --------------
__global__ void __launch_bounds__(256) k_sqk(const float* __restrict__ qin,
                                             const float* __restrict__ kin) {
    extern __shared__ float sWE[];                    // [1024][16]
    __shared__ float sred[8];
    int side = blockIdx.y;
    const float* WE = side ? g_WkE : g_WqE;
    int tid = threadIdx.x;
    {
        const float4* src = (const float4*)WE;
        float4* dst = (float4*)sWE;
        for (int t = tid; t < (EMBED * HEADS) / 4; t += 256) dst[t] = src[t];
    }
    __syncthreads();

    int n  = tid & 15;
    int rl = tid >> 4;
    int row = blockIdx.x * 16 + rl;
    const float* xr = (side ? kin : qin) + (size_t)row * EMBED;

    float s0 = 0.f, s1 = 0.f, s2 = 0.f, s3 = 0.f;
#pragma unroll 4
    for (int e = 0; e < EMBED; e += 4) {
        float4 xv = *(const float4*)(xr + e);
        s0 += xv.x * sWE[(e + 0) * 16 + n];
        s1 += xv.y * sWE[(e + 1) * 16 + n];
        s2 += xv.z * sWE[(e + 2) * 16 + n];
        s3 += xv.w * sWE[(e + 3) * 16 + n];
    }
    float s = (s0 + s1) + (s2 + s3);
    if (!side) s += g_bqE[n];
    int b = row >> 10, i = row & 1023;
    float* dst = side ? g_SK : g_SQ;
    dst[((b * HEADS + n) << 10) + i] = s;

    if (side) {
        float a = fabsf(s);
        int lane = tid & 31, wid = tid >> 5;
#pragma unroll
        for (int o = 16; o; o >>= 1) a = fmaxf(a, __shfl_xor_sync(0xffffffffu, a, o));
        if (lane == 0) sred[wid] = a;
        __syncthreads();
        if (tid == 0) {
            float mx = 0.f;
#pragma unroll
            for (int w2 = 0; w2 < 8; w2++) mx = fmaxf(mx, sred[w2]);
            atomicMax(&g_skmax_bits, __float_as_uint(mx));
        }
    }
}

// ---------------- K1b: Chebyshev nodes/weights (runtime Y) -------------------------
__global__ void k_cheb() {
    int m = threadIdx.x;                       // 0..31
    float smax = __uint_as_float(g_skmax_bits);
    double Y = (double)smax * 1.0005 + 1e-6;
    double th = (2.0 * m + 1.0) * (3.14159265358979323846 / (2.0 * MCH));
    g_ynodes[m] = (float)(Y * cos(th));
    g_wbar[m]   = (float)(((m & 1) ? -1.0 : 1.0) * sin(th));
}

// ---------------- K2/K4: FFMA2 GEMM  C[M,1024] = A[M,1024] @ W[1024,1024] ----------
template <int MODE>
__global__ void __launch_bounds__(256, 2) k_gemm(const float* __restrict__ A,
                                                 const float* __restrict__ W,
                                                 const float* __restrict__ bias,
                                                 float* __restrict__ Cout) {
    const int BM = 128, BN = 128, BK = 16;
    __shared__ float As[BK][BM];
    __shared__ float Bs[BK][BN];

    int tid = threadIdx.x;
    int tx = tid & 15;
    int ty = tid >> 4;
    int m0 = blockIdx.y * BM;
    int n0 = blockIdx.x * BN;

    u64 acc[8][4];
#pragma unroll
    for (int a = 0; a < 8; a++)
#pragma unroll
        for (int b = 0; b < 4; b++) acc[a][b] = 0ull;

    for (int kt = 0; kt < EMBED; kt += BK) {
#pragma unroll
        for (int s = 0; s < 2; s++) {
            int id = tid * 2 + s;
            int m = id >> 2;
            int kq = (id & 3) * 4;
            float4 av = *(const float4*)(A + (size_t)(m0 + m) * EMBED + kt + kq);
            As[kq + 0][m] = av.x;
            As[kq + 1][m] = av.y;
            As[kq + 2][m] = av.z;
            As[kq + 3][m] = av.w;
        }
#pragma unroll
        for (int s = 0; s < 2; s++) {
            int id = tid * 2 + s;
            int kb = id >> 5;
            int nf = id & 31;
            *(float4*)&Bs[kb][nf * 4] =
                *(const float4*)(W + (size_t)(kt + kb) * (HEADS * HDIM) + n0 + nf * 4);
        }
        __syncthreads();

#pragma unroll
        for (int kk = 0; kk < BK; kk++) {
            F4U2 a0, a1, b0, b1;
            a0.f4 = *(const float4*)&As[kk][ty * 8];
            a1.f4 = *(const float4*)&As[kk][ty * 8 + 4];
            b0.f4 = *(const float4*)&Bs[kk][tx * 8];
            b1.f4 = *(const float4*)&Bs[kk][tx * 8 + 4];
            u64 bp[4] = { b0.u2[0], b0.u2[1], b1.u2[0], b1.u2[1] };
            u64 ad[8];
#pragma unroll
            for (int mi = 0; mi < 4; mi++) { ad[mi] = dup2(a0.f[mi]); ad[mi + 4] = dup2(a1.f[mi]); }
#pragma unroll
            for (int mi = 0; mi < 8; mi++)
#pragma unroll
                for (int nj = 0; nj < 4; nj++)
                    acc[mi][nj] = fma2(ad[mi], bp[nj], acc[mi][nj]);
        }
        __syncthreads();
    }

    if (MODE == 0) {
        int col = n0 + tx * 8;
        F4U2 bv0, bv1;
        bv0.f4 = *(const float4*)(bias + col);
        bv1.f4 = *(const float4*)(bias + col + 4);
#pragma unroll
        for (int mi = 0; mi < 8; mi++) {
            int row = m0 + ty * 8 + mi;
            F4U2 o0, o1;
            o0.u2[0] = acc[mi][0]; o0.u2[1] = acc[mi][1];
            o1.u2[0] = acc[mi][2]; o1.u2[1] = acc[mi][3];
#pragma unroll
            for (int c = 0; c < 4; c++) { o0.f[c] += bv0.f[c]; o1.f[c] += bv1.f[c]; }
            *(float4*)(Cout + (size_t)row * (HEADS * HDIM) + col)     = o0.f4;
            *(float4*)(Cout + (size_t)row * (HEADS * HDIM) + col + 4) = o1.f4;
        }
    } else {
        int col = n0 + tx * 8;
        int head = col >> 6;
        int d = col & 63;
#pragma unroll
        for (int mi = 0; mi < 8; mi++) {
            int row = m0 + ty * 8 + mi;
            int b = row >> 10, j = row & 1023;
            float* dst = g_vh + ((((size_t)(b * HEADS + head)) << 10) + j) * HDIM + d;
            F4U2 o0, o1;
            o0.u2[0] = acc[mi][0]; o0.u2[1] = acc[mi][1];
            o1.u2[0] = acc[mi][2]; o1.u2[1] = acc[mi][3];
            *(float4*)(dst)     = o0.f4;
            *(float4*)(dst + 4) = o1.f4;
        }
    }
}

// ---------------- K3a: key moments  S_m, T_m[d] per (b,n) --------------------------
// psi_m(sk_j) barycentric; T[m][d] = sum_j psi_jm * v[j][d]; S[m] = sum_j psi_jm
__global__ void __launch_bounds__(256) k_psi() {
    __shared__ float psi[128 * 33];   // [j][m], padded
    __shared__ float sv[128 * 64];    // V tile 32KB
    __shared__ float yn[MCH], wb[MCH];

    int bn = blockIdx.x;              // 0..63
    int tid = threadIdx.x;
    if (tid < MCH) { yn[tid] = g_ynodes[tid]; wb[tid] = g_wbar[tid]; }

    const float* SK = g_SK + (bn << 10);
    const float* V  = g_vh + (((size_t)bn) << 10) * HDIM;

    int m  = tid & 31;
    int dg = tid >> 5;                // 0..7 -> d chunk of 8
    float accT[8];
#pragma unroll
    for (int c = 0; c < 8; c++) accT[c] = 0.f;
    float accS = 0.f;

    for (int jt = 0; jt < LSEQ; jt += 128) {
        __syncthreads();
        {   // V tile load
            const float4* gs = (const float4*)(V + (size_t)jt * HDIM);
            float4* sd = (float4*)sv;
#pragma unroll
            for (int q = 0; q < 8; q++) sd[tid + q * 256] = gs[tid + q * 256];
        }
        if (tid < 128) {
            float y = SK[jt + tid];
            float t[MCH];
            float den = 0.f;
#pragma unroll
            for (int k2 = 0; k2 < MCH; k2++) {
                float d = y - yn[k2];
                d = (fabsf(d) < 1e-12f) ? 1e-12f : d;
                t[k2] = wb[k2] * frcp(d);
                den += t[k2];
            }
            float ri = frcp(den);
#pragma unroll
            for (int k2 = 0; k2 < MCH; k2++) psi[tid * 33 + k2] = t[k2] * ri;
        }
        __syncthreads();

#pragma unroll 2
        for (int j = 0; j < 128; j++) {
            float p = psi[j * 33 + m];
            const float* vr = sv + j * 64 + dg * 8;
            float4 v0 = *(const float4*)vr;
            float4 v1 = *(const float4*)(vr + 4);
            accT[0] += p * v0.x; accT[1] += p * v0.y;
            accT[2] += p * v0.z; accT[3] += p * v0.w;
            accT[4] += p * v1.x; accT[5] += p * v1.y;
            accT[6] += p * v1.z; accT[7] += p * v1.w;
            if (dg == 0) accS += p;
        }
    }

    float* Tp = g_T + (((size_t)bn * MCH) + m) * HDIM + dg * 8;
    float4 o0, o1;
    o0.x = accT[0]; o0.y = accT[1]; o0.z = accT[2]; o0.w = accT[3];
    o1.x = accT[4]; o1.y = accT[5]; o1.z = accT[6]; o1.w = accT[7];
    *(float4*)Tp = o0;
    *(float4*)(Tp + 4) = o1;
    if (dg == 0) g_S[bn * MCH + m] = accS;
}

// ---------------- K3b: query side  out = (sum_m phi_m T_m)/(sum_m phi_m S_m) -------
__global__ void __launch_bounds__(256) k_query() {
    __shared__ float sT[MCH * 64];    // 8KB
    __shared__ float sS[MCH], syn[MCH];

    int bn = blockIdx.y;
    int b = bn >> 4, n = bn & 15;
    int tid = threadIdx.x;
    int i = blockIdx.x * 256 + tid;

    {   // load T, S, nodes
        const float4* gs = (const float4*)(g_T + (size_t)bn * MCH * HDIM);
        float4* sd = (float4*)sT;
        sd[tid] = gs[tid];
        sd[tid + 256] = gs[tid + 256];
        if (tid < MCH) { sS[tid] = g_S[bn * MCH + tid]; syn[tid] = g_ynodes[tid]; }
    }
    __syncthreads();

    float sq = g_SQ[(bn << 10) + i];
    float phi[MCH];
    float den = 0.f;
#pragma unroll
    for (int m = 0; m < MCH; m++) {
        float u = __expf(2.f * (sq + syn[m]));
        float t = (u - 1.f) * frcp(u + 1.f);
        float p = __expf(t);
        phi[m] = p;
        den += p * sS[m];
    }

    u64 acc[32];
#pragma unroll
    for (int c = 0; c < 32; c++) acc[c] = 0ull;
#pragma unroll
    for (int m = 0; m < MCH; m++) {
        u64 p2 = dup2(phi[m]);
        const float* Tr = sT + m * 64;
#pragma unroll
        for (int q = 0; q < 16; q++) {
            F4U2 tv; tv.f4 = *(const float4*)(Tr + q * 4);
            acc[q * 2 + 0] = fma2(p2, tv.u2[0], acc[q * 2 + 0]);
            acc[q * 2 + 1] = fma2(p2, tv.u2[1], acc[q * 2 + 1]);
        }
    }

    float inv = frcp(den);
    float* outp = g_att + (size_t)(b * LSEQ + i) * (HEADS * HDIM) + n * HDIM;
#pragma unroll
    for (int q = 0; q < 16; q++) {
        F4U2 o;
        o.u2[0] = acc[q * 2 + 0];
        o.u2[1] = acc[q * 2 + 1];
#pragma unroll
        for (int c = 0; c < 4; c++) o.f[c] *= inv;
        *(float4*)(outp + q * 4) = o.f4;
    }
}

// ---------------- K5: layernorm ----------------------------------------------------
__global__ void __launch_bounds__(256) k_ln(float* __restrict__ y,
                                            const float* __restrict__ gamma,
                                            const float* __restrict__ beta) {
    int row = blockIdx.x, tid = threadIdx.x;
    float4* yp = (float4*)(y + (size_t)row * 1024);
    float4 v = yp[tid];
    float s  = v.x + v.y + v.z + v.w;
    float ss = v.x * v.x + v.y * v.y + v.z * v.z + v.w * v.w;

    __shared__ float red[16];
    int lane = tid & 31, wid = tid >> 5;
#pragma unroll
    for (int o = 16; o; o >>= 1) {
        s  += __shfl_xor_sync(0xffffffffu, s,  o);
        ss += __shfl_xor_sync(0xffffffffu, ss, o);
    }
    if (lane == 0) { red[wid] = s; red[wid + 8] = ss; }
    __syncthreads();
    if (tid == 0) {
        float S = 0.f, SS = 0.f;
        for (int w = 0; w < 8; w++) { S += red[w]; SS += red[w + 8]; }
        red[0] = S; red[1] = SS;
    }
    __syncthreads();
    float mean = red[0] * (1.0f / 1024.0f);
    float var  = red[1] * (1.0f / 1024.0f) - mean * mean;
    float rr = rsqrtf(var + 1e-6f);

    float4 g  = ((const float4*)gamma)[tid];
    float4 bb = ((const float4*)beta)[tid];
    float4 o;
    o.x = (v.x - mean) * rr * g.x + bb.x;
    o.y = (v.y - mean) * rr * g.y + bb.y;
    o.z = (v.z - mean) * rr * g.z + bb.z;
    o.w = (v.w - mean) * rr * g.w + bb.w;
    yp[tid] = o;
}

// ---------------- launcher ----------------------------------------------------------
extern "C" void kernel_launch(void* const* d_in, const int* in_sizes, int n_in,
                              void* d_out, int out_size) {
    (void)n_in; (void)out_size;
    const float* k_in  = (const float*)d_in[0];
    const float* q_in  = (const float*)d_in[1];
    const float* v_in  = (const float*)d_in[2];
    const float* Wq    = (const float*)d_in[3];
    const float* bq    = (const float*)d_in[4];
    const float* Wk    = (const float*)d_in[5];
    const float* Wv    = (const float*)d_in[6];
    const float* Wp    = (const float*)d_in[7];
    const float* bp    = (const float*)d_in[8];
    const float* aw    = (const float*)d_in[9];
    const float* gamma = (const float*)d_in[10];
    const float* beta  = (const float*)d_in[11];
    float* out = (float*)d_out;

    int B = in_sizes[0] / (LSEQ * EMBED);   // 4
    int M = B * LSEQ;                        // 4096

    float* p_att = nullptr;
    cudaGetSymbolAddress((void**)&p_att, g_att);

    cudaFuncSetAttribute(k_sqk, cudaFuncAttributeMaxDynamicSharedMemorySize, 65536);

    k_weff<<<128, 256>>>(Wq, Wk, bq, aw);
    k_sqk<<<dim3(M / 16, 2), 256, 65536>>>(q_in, k_in);
    k_cheb<<<1, MCH>>>();
    k_gemm<1><<<dim3((HEADS * HDIM) / 128, M / 128), 256>>>(v_in, Wv, nullptr, nullptr);
    k_psi<<<B * HEADS, 256>>>();
    k_query<<<dim3(LSEQ / 256, B * HEADS), 256>>>();
    k_gemm<0><<<dim3(1024 / 128, M / 128), 256>>>(p_att, Wp, bp, out);
    k_ln<<<M, 256>>>(out, gamma, beta);
}

// round 5
// speedup vs baseline: 1.5049x; 1.0058x over previous
#include <cuda_runtime.h>
#include <cstdint>

#define EMBED 1024
#define HEADS 16
#define HDIM  64
#define LSEQ  1024
#define MAXB  4
#define MCH   32          // Chebyshev rank
#define OUTD  1024

typedef unsigned long long u64;

// ---------------- packed f32x2 helpers (Blackwell FFMA2) ---------------------------
__device__ __forceinline__ u64 fma2(u64 a, u64 b, u64 c) {
    u64 d;
    asm("fma.rn.f32x2 %0, %1, %2, %3;" : "=l"(d) : "l"(a), "l"(b), "l"(c));
    return d;
}
__device__ __forceinline__ u64 dup2(float x) {
    u64 d;
    unsigned u = __float_as_uint(x);
    asm("mov.b64 %0, {%1, %1};" : "=l"(d) : "r"(u));
    return d;
}
union F4U2 { float4 f4; u64 u2[2]; float f[4]; };

__device__ __forceinline__ float frcp(float x) {
    float r; asm("rcp.approx.f32 %0, %1;" : "=f"(r) : "f"(x)); return r;
}

// ---------------- scratch ----------------------------------------------------------
__device__ float g_WqE[EMBED * HEADS];
__device__ float g_WkE[EMBED * HEADS];
__device__ float g_bqE[HEADS];
__device__ float g_SQ[MAXB * HEADS * LSEQ];     // raw sq  [b][n][i]
__device__ float g_SK[MAXB * HEADS * LSEQ];     // raw sk  [b][n][j]
__device__ unsigned g_skmax_bits;
__device__ float g_ynodes[MCH];
__device__ float g_wbar[MCH];
__device__ float g_Psi[(size_t)MAXB * 512 * LSEQ];   // [b][n*32+m][j]
__device__ float g_S[MAXB * HEADS * MCH];             // [bn][m]
__device__ float g_P[(size_t)MAXB * 512 * EMBED];     // [b][n*32+m][e]
__device__ float g_T[(size_t)MAXB * HEADS * MCH * HDIM];   // [bn][m][d]
__device__ float g_U[(size_t)MAXB * 512 * OUTD];      // [b][n*32+m][o]
__device__ float g_Phi[(size_t)MAXB * LSEQ * 512];    // [b][i][n*32+m]  (phi/den)

// ---------------- K0: effective weights --------------------------------------------
__global__ void k_weff(const float* __restrict__ Wq, const float* __restrict__ Wk,
                       const float* __restrict__ bq, const float* __restrict__ aw) {
    int t = blockIdx.x * blockDim.x + threadIdx.x;
    if (t == 0) g_skmax_bits = 0u;
    int side = t >> 14;
    int u = t & 16383;
    int e = u >> 4, n = u & 15;
    const float* W = side ? Wk : Wq;
    const float* w = aw + side * HDIM;
    float s = 0.f;
#pragma unroll 8
    for (int d = 0; d < HDIM; d++)
        s += W[(size_t)e * (HEADS * HDIM) + n * HDIM + d] * w[d];
    if (side) g_WkE[e * 16 + n] = s;
    else      g_WqE[e * 16 + n] = s;
    if (!side && e == 0) {
        float sb = 0.f;
#pragma unroll 8
        for (int d = 0; d < HDIM; d++) sb += bq[n * HDIM + d] * w[d];
        g_bqE[n] = sb;
    }
}

// ---------------- K1: sq/sk = x @ WE (+bqE); track max|sk| -------------------------
__global__ void __launch_bounds__(256) k_sqk(const float* __restrict__ qin,
                                             const float* __restrict__ kin) {
    extern __shared__ float sWE[];                    // [1024][16]
    __shared__ float sred[8];
    int side = blockIdx.y;
    const float* WE = side ? g_WkE : g_WqE;
    int tid = threadIdx.x;
    {
        const float4* src = (const float4*)WE;
        float4* dst = (float4*)sWE;
        for (int t = tid; t < (EMBED * HEADS) / 4; t += 256) dst[t] = src[t];
    }
    __syncthreads();

    int n  = tid & 15;
    int rl = tid >> 4;
    int row = blockIdx.x * 16 + rl;
    const float* xr = (side ? kin : qin) + (size_t)row * EMBED;

    float s0 = 0.f, s1 = 0.f, s2 = 0.f, s3 = 0.f;
#pragma unroll 4
    for (int e = 0; e < EMBED; e += 4) {
        float4 xv = *(const float4*)(xr + e);
        s0 += xv.x * sWE[(e + 0) * 16 + n];
        s1 += xv.y * sWE[(e + 1) * 16 + n];
        s2 += xv.z * sWE[(e + 2) * 16 + n];
        s3 += xv.w * sWE[(e + 3) * 16 + n];
    }
    float s = (s0 + s1) + (s2 + s3);
    if (!side) s += g_bqE[n];
    int b = row >> 10, i = row & 1023;
    float* dst = side ? g_SK : g_SQ;
    dst[((b * HEADS + n) << 10) + i] = s;

    if (side) {
        float a = fabsf(s);
        int lane = tid & 31, wid = tid >> 5;
#pragma unroll
        for (int o = 16; o; o >>= 1) a = fmaxf(a, __shfl_xor_sync(0xffffffffu, a, o));
        if (lane == 0) sred[wid] = a;
        __syncthreads();
        if (tid == 0) {
            float mx = 0.f;
#pragma unroll
            for (int w2 = 0; w2 < 8; w2++) mx = fmaxf(mx, sred[w2]);
            atomicMax(&g_skmax_bits, __float_as_uint(mx));
        }
    }
}

// ---------------- K1b: Chebyshev nodes/weights -------------------------------------
__global__ void k_cheb() {
    int m = threadIdx.x;
    float smax = __uint_as_float(g_skmax_bits);
    double Y = (double)smax * 1.0005 + 1e-6;
    double th = (2.0 * m + 1.0) * (3.14159265358979323846 / (2.0 * MCH));
    g_ynodes[m] = (float)(Y * cos(th));
    g_wbar[m]   = (float)(((m & 1) ? -1.0 : 1.0) * sin(th));
}

// ---------------- K2a: materialize Psi[b][n*32+m][j] -------------------------------
// grid (4 jchunks, 64 bn), 256 threads
__global__ void __launch_bounds__(256) k_psimat() {
    __shared__ float sp[256][33];
    __shared__ float yn[MCH], wb[MCH];
    int bn = blockIdx.y;
    int b = bn >> 4, n = bn & 15;
    int j0 = blockIdx.x * 256;
    int tid = threadIdx.x;
    if (tid < MCH) { yn[tid] = g_ynodes[tid]; wb[tid] = g_wbar[tid]; }
    __syncthreads();

    {
        float y = g_SK[(bn << 10) + j0 + tid];
        float t[MCH];
        float den = 0.f;
#pragma unroll
        for (int m = 0; m < MCH; m++) {
            float d = y - yn[m];
            d = (fabsf(d) < 1e-12f) ? 1e-12f : d;
            t[m] = wb[m] * frcp(d);
            den += t[m];
        }
        float ri = frcp(den);
#pragma unroll
        for (int m = 0; m < MCH; m++) sp[tid][m] = t[m] * ri;
    }
    __syncthreads();

    // transposed write: rows = m, 256 j columns
    int r  = tid >> 3;              // m 0..31
    int cg = (tid & 7) * 32;        // col group
    float* dst = g_Psi + (((size_t)b * 512) + n * 32 + r) * LSEQ + j0 + cg;
#pragma unroll
    for (int q = 0; q < 32; q += 4) {
        float4 o;
        o.x = sp[cg + q + 0][r];
        o.y = sp[cg + q + 1][r];
        o.z = sp[cg + q + 2][r];
        o.w = sp[cg + q + 3][r];
        *(float4*)(dst + q) = o;
    }
}

// ---------------- K2b: S[bn][m] = sum_j psi ----------------------------------------
__global__ void __launch_bounds__(256) k_S() {
    __shared__ float sp[256 * 33];
    __shared__ float yn[MCH], wb[MCH];
    int bn = blockIdx.x;
    int tid = threadIdx.x;
    if (tid < MCH) { yn[tid] = g_ynodes[tid]; wb[tid] = g_wbar[tid]; }
    __syncthreads();

    float acc[MCH];
#pragma unroll
    for (int m = 0; m < MCH; m++) acc[m] = 0.f;
#pragma unroll
    for (int s = 0; s < 4; s++) {
        float y = g_SK[(bn << 10) + tid + s * 256];
        float t[MCH];
        float den = 0.f;
#pragma unroll
        for (int m = 0; m < MCH; m++) {
            float d = y - yn[m];
            d = (fabsf(d) < 1e-12f) ? 1e-12f : d;
            t[m] = wb[m] * frcp(d);
            den += t[m];
        }
        float ri = frcp(den);
#pragma unroll
        for (int m = 0; m < MCH; m++) acc[m] += t[m] * ri;
    }
#pragma unroll
    for (int m = 0; m < MCH; m++) sp[tid * 33 + m] = acc[m];
    __syncthreads();
    if (tid < MCH) {
        float s = 0.f;
        for (int r = 0; r < 256; r++) s += sp[r * 33 + tid];
        g_S[bn * MCH + tid] = s;
    }
}

// ---------------- K3: generic batched FFMA2 GEMM C = A@B (+bias) -------------------
// C[M,1024] = A[M,K] @ B[K,1024]; grid (N/128, M/128, batch)
template <bool BIAS>
__global__ void __launch_bounds__(256, 2) k_gemm2(const float* __restrict__ A,
                                                  const float* __restrict__ B,
                                                  const float* __restrict__ bias,
                                                  float* __restrict__ C,
                                                  int K, int lda,
                                                  size_t sA, size_t sB, size_t sC) {
    const int BK = 16;
    __shared__ float As[BK][128];
    __shared__ float Bs[BK][128];

    A += blockIdx.z * sA;
    B += blockIdx.z * sB;
    C += blockIdx.z * sC;

    int tid = threadIdx.x;
    int tx = tid & 15;
    int ty = tid >> 4;
    int m0 = blockIdx.y * 128;
    int n0 = blockIdx.x * 128;

    u64 acc[8][4];
#pragma unroll
    for (int a = 0; a < 8; a++)
#pragma unroll
        for (int b2 = 0; b2 < 4; b2++) acc[a][b2] = 0ull;

    for (int kt = 0; kt < K; kt += BK) {
#pragma unroll
        for (int s = 0; s < 2; s++) {
            int id = tid * 2 + s;
            int m = id >> 2;
            int kq = (id & 3) * 4;
            float4 av = *(const float4*)(A + (size_t)(m0 + m) * lda + kt + kq);
            As[kq + 0][m] = av.x;
            As[kq + 1][m] = av.y;
            As[kq + 2][m] = av.z;
            As[kq + 3][m] = av.w;
        }
#pragma unroll
        for (int s = 0; s < 2; s++) {
            int id = tid * 2 + s;
            int kb = id >> 5;
            int nf = id & 31;
            *(float4*)&Bs[kb][nf * 4] =
                *(const float4*)(B + (size_t)(kt + kb) * 1024 + n0 + nf * 4);
        }
        __syncthreads();

#pragma unroll
        for (int kk = 0; kk < BK; kk++) {
            F4U2 a0, a1, b0, b1;
            a0.f4 = *(const float4*)&As[kk][ty * 8];
            a1.f4 = *(const float4*)&As[kk][ty * 8 + 4];
            b0.f4 = *(const float4*)&Bs[kk][tx * 8];
            b1.f4 = *(const float4*)&Bs[kk][tx * 8 + 4];
            u64 bp[4] = { b0.u2[0], b0.u2[1], b1.u2[0], b1.u2[1] };
            u64 ad[8];
#pragma unroll
            for (int mi = 0; mi < 4; mi++) { ad[mi] = dup2(a0.f[mi]); ad[mi + 4] = dup2(a1.f[mi]); }
#pragma unroll
            for (int mi = 0; mi < 8; mi++)
#pragma unroll
                for (int nj = 0; nj < 4; nj++)
                    acc[mi][nj] = fma2(ad[mi], bp[nj], acc[mi][nj]);
        }
        __syncthreads();
    }

    int col = n0 + tx * 8;
    F4U2 bv0, bv1;
    if (BIAS) {
        bv0.f4 = *(const float4*)(bias + col);
        bv1.f4 = *(const float4*)(bias + col + 4);
    }
#pragma unroll
    for (int mi = 0; mi < 8; mi++) {
        int row = m0 + ty * 8 + mi;
        F4U2 o0, o1;
        o0.u2[0] = acc[mi][0]; o0.u2[1] = acc[mi][1];
        o1.u2[0] = acc[mi][2]; o1.u2[1] = acc[mi][3];
        if (BIAS) {
#pragma unroll
            for (int c = 0; c < 4; c++) { o0.f[c] += bv0.f[c]; o1.f[c] += bv1.f[c]; }
        }
        *(float4*)(C + (size_t)row * 1024 + col)     = o0.f4;
        *(float4*)(C + (size_t)row * 1024 + col + 4) = o1.f4;
    }
}

// ---------------- K4: T[bn][m][d] = sum_e P[b][n*32+m][e] * Wv[e][n*64+d] ----------
// grid 64 (bn), 256 threads
__global__ void __launch_bounds__(256) k_T(const float* __restrict__ Wv) {
    __shared__ float sp[32][64];   // P chunk
    __shared__ float sw[64][64];   // Wv chunk
    int bn = blockIdx.x;
    int b = bn >> 4, n = bn & 15;
    int tid = threadIdx.x;
    int m  = tid >> 3;
    int dq = (tid & 7) * 8;

    const float* P = g_P + ((size_t)b * 512 + n * 32) * EMBED;

    u64 acc[4];
#pragma unroll
    for (int c = 0; c < 4; c++) acc[c] = 0ull;

    for (int e0 = 0; e0 < EMBED; e0 += 64) {
        __syncthreads();
#pragma unroll
        for (int s = 0; s < 2; s++) {
            int f4 = tid + s * 256;          // 0..511
            int row = f4 >> 4, c4 = (f4 & 15) * 4;
            *(float4*)&sp[row][c4] = *(const float4*)(P + (size_t)row * EMBED + e0 + c4);
        }
#pragma unroll
        for (int s = 0; s < 4; s++) {
            int f4 = tid + s * 256;          // 0..1023
            int row = f4 >> 4, c4 = (f4 & 15) * 4;
            *(float4*)&sw[row][c4] = *(const float4*)(Wv + (size_t)(e0 + row) * (HEADS * HDIM) + n * 64 + c4);
        }
        __syncthreads();

#pragma unroll 4
        for (int e = 0; e < 64; e++) {
            u64 p2 = dup2(sp[m][e]);
            F4U2 w0, w1;
            w0.f4 = *(const float4*)&sw[e][dq];
            w1.f4 = *(const float4*)&sw[e][dq + 4];
            acc[0] = fma2(p2, w0.u2[0], acc[0]);
            acc[1] = fma2(p2, w0.u2[1], acc[1]);
            acc[2] = fma2(p2, w1.u2[0], acc[2]);
            acc[3] = fma2(p2, w1.u2[1], acc[3]);
        }
    }

    float* Tp = g_T + ((size_t)bn * MCH + m) * HDIM + dq;
    F4U2 o0, o1;
    o0.u2[0] = acc[0]; o0.u2[1] = acc[1];
    o1.u2[0] = acc[2]; o1.u2[1] = acc[3];
    *(float4*)Tp = o0.f4;
    *(float4*)(Tp + 4) = o1.f4;
}

// ---------------- K5: U[b][n*32+m][o] = sum_d T[bn][m][d] * Wp[n*64+d][o] ----------
// grid (4 ochunks, 64 bn), 256 threads
__global__ void __launch_bounds__(256) k_U(const float* __restrict__ Wp) {
    __shared__ float sT[32][64];
    __shared__ float sW[16][256];
    int bn = blockIdx.y;
    int b = bn >> 4, n = bn & 15;
    int c0 = blockIdx.x * 256;
    int tid = threadIdx.x;
    int m = tid >> 3;
    int cq = (tid & 7) * 32;

#pragma unroll
    for (int s = 0; s < 2; s++) {
        int f4 = tid + s * 256;
        int row = f4 >> 4, c4 = (f4 & 15) * 4;
        *(float4*)&sT[row][c4] = *(const float4*)(g_T + (size_t)bn * (MCH * HDIM) + row * HDIM + c4);
    }

    u64 acc[16];
#pragma unroll
    for (int c = 0; c < 16; c++) acc[c] = 0ull;

    for (int dt = 0; dt < 4; dt++) {
        __syncthreads();
#pragma unroll
        for (int s = 0; s < 4; s++) {
            int f4 = tid + s * 256;          // 0..1023
            int row = f4 >> 6, c4 = (f4 & 63) * 4;
            *(float4*)&sW[row][c4] =
                *(const float4*)(Wp + (size_t)(n * 64 + dt * 16 + row) * OUTD + c0 + c4);
        }
        __syncthreads();

#pragma unroll
        for (int d = 0; d < 16; d++) {
            u64 t2 = dup2(sT[m][dt * 16 + d]);
#pragma unroll
            for (int q = 0; q < 8; q++) {
                F4U2 w; w.f4 = *(const float4*)&sW[d][cq + q * 4];
                acc[q * 2 + 0] = fma2(t2, w.u2[0], acc[q * 2 + 0]);
                acc[q * 2 + 1] = fma2(t2, w.u2[1], acc[q * 2 + 1]);
            }
        }
    }

    float* Up = g_U + (((size_t)b * 512) + n * 32 + m) * OUTD + c0 + cq;
#pragma unroll
    for (int q = 0; q < 8; q++) {
        F4U2 o;
        o.u2[0] = acc[q * 2 + 0];
        o.u2[1] = acc[q * 2 + 1];
        *(float4*)(Up + q * 4) = o.f4;
    }
}

// ---------------- K6: Phi~[b][i][n*32+m] = phi/den ---------------------------------
// grid (64 ichunks, B), block 256 = 16 i x 16 n
__global__ void __launch_bounds__(256) k_phiq() {
    __shared__ float syn[MCH];
    __shared__ float sS[16][MCH];
    int b = blockIdx.y;
    int tid = threadIdx.x;
    int n = tid & 15;
    int ir = tid >> 4;
    int i = blockIdx.x * 16 + ir;

    if (tid < MCH) syn[tid] = g_ynodes[tid];
    if (tid < 256) {
        // load S for this b's 16 heads: 512 floats
        for (int t = tid; t < 16 * MCH; t += 256)
            sS[t >> 5][t & 31] = g_S[(b * 16 + (t >> 5)) * MCH + (t & 31)];
    }
    __syncthreads();

    float sq = g_SQ[((b * 16 + n) << 10) + i];
    float phi[MCH];
    float den = 0.f;
#pragma unroll
    for (int m = 0; m < MCH; m++) {
        float u = __expf(2.f * (sq + syn[m]));
        float t = (u - 1.f) * frcp(u + 1.f);
        float p = __expf(t);
        phi[m] = p;
        den += p * sS[n][m];
    }
    float inv = frcp(den);

    float* dst = g_Phi + (((size_t)b << 10) + i) * 512 + n * 32;
#pragma unroll
    for (int q = 0; q < 8; q++) {
        float4 o;
        o.x = phi[q * 4 + 0] * inv;
        o.y = phi[q * 4 + 1] * inv;
        o.z = phi[q * 4 + 2] * inv;
        o.w = phi[q * 4 + 3] * inv;
        *(float4*)(dst + q * 4) = o;
    }
}

// ---------------- K7: layernorm ----------------------------------------------------
__global__ void __launch_bounds__(256) k_ln(float* __restrict__ y,
                                            const float* __restrict__ gamma,
                                            const float* __restrict__ beta) {
    int row = blockIdx.x, tid = threadIdx.x;
    float4* yp = (float4*)(y + (size_t)row * 1024);
    float4 v = yp[tid];
    float s  = v.x + v.y + v.z + v.w;
    float ss = v.x * v.x + v.y * v.y + v.z * v.z + v.w * v.w;

    __shared__ float red[16];
    int lane = tid & 31, wid = tid >> 5;
#pragma unroll
    for (int o = 16; o; o >>= 1) {
        s  += __shfl_xor_sync(0xffffffffu, s,  o);
        ss += __shfl_xor_sync(0xffffffffu, ss, o);
    }
    if (lane == 0) { red[wid] = s; red[wid + 8] = ss; }
    __syncthreads();
    if (tid == 0) {
        float S = 0.f, SS = 0.f;
        for (int w = 0; w < 8; w++) { S += red[w]; SS += red[w + 8]; }
        red[0] = S; red[1] = SS;
    }
    __syncthreads();
    float mean = red[0] * (1.0f / 1024.0f);
    float var  = red[1] * (1.0f / 1024.0f) - mean * mean;
    float rr = rsqrtf(var + 1e-6f);

    float4 g  = ((const float4*)gamma)[tid];
    float4 bb = ((const float4*)beta)[tid];
    float4 o;
    o.x = (v.x - mean) * rr * g.x + bb.x;
    o.y = (v.y - mean) * rr * g.y + bb.y;
    o.z = (v.z - mean) * rr * g.z + bb.z;
    o.w = (v.w - mean) * rr * g.w + bb.w;
    yp[tid] = o;
}

// ---------------- launcher ----------------------------------------------------------
extern "C" void kernel_launch(void* const* d_in, const int* in_sizes, int n_in,
                              void* d_out, int out_size) {
    (void)n_in; (void)out_size;
    const float* k_in  = (const float*)d_in[0];
    const float* q_in  = (const float*)d_in[1];
    const float* v_in  = (const float*)d_in[2];
    const float* Wq    = (const float*)d_in[3];
    const float* bq    = (const float*)d_in[4];
    const float* Wk    = (const float*)d_in[5];
    const float* Wv    = (const float*)d_in[6];
    const float* Wp    = (const float*)d_in[7];
    const float* bp    = (const float*)d_in[8];
    const float* aw    = (const float*)d_in[9];
    const float* gamma = (const float*)d_in[10];
    const float* beta  = (const float*)d_in[11];
    float* out = (float*)d_out;

    int B = in_sizes[0] / (LSEQ * EMBED);   // 4
    int M = B * LSEQ;                        // 4096

    float *p_Psi = nullptr, *p_P = nullptr, *p_Phi = nullptr, *p_U = nullptr;
    cudaGetSymbolAddress((void**)&p_Psi, g_Psi);
    cudaGetSymbolAddress((void**)&p_P,   g_P);
    cudaGetSymbolAddress((void**)&p_Phi, g_Phi);
    cudaGetSymbolAddress((void**)&p_U,   g_U);

    cudaFuncSetAttribute(k_sqk, cudaFuncAttributeMaxDynamicSharedMemorySize, 65536);

    k_weff<<<128, 256>>>(Wq, Wk, bq, aw);
    k_sqk<<<dim3(M / 16, 2), 256, 65536>>>(q_in, k_in);
    k_cheb<<<1, MCH>>>();
    k_psimat<<<dim3(LSEQ / 256, B * HEADS), 256>>>();
    k_S<<<B * HEADS, 256>>>();
    // P[b] = Psi_b [512 x 1024] @ v_b [1024 x 1024]
    k_gemm2<false><<<dim3(8, 4, B), 256>>>(p_Psi, v_in, nullptr, p_P,
                                           1024, 1024,
                                           (size_t)512 * 1024, (size_t)1024 * 1024,
                                           (size_t)512 * 1024);
    k_T<<<B * HEADS, 256>>>(Wv);
    k_U<<<dim3(4, B * HEADS), 256>>>(Wp);
    k_phiq<<<dim3(LSEQ / 16, B), 256>>>();
    // out[b] = Phi_b [1024 x 512] @ U_b [512 x 1024] + bp
    k_gemm2<true><<<dim3(8, 8, B), 256>>>(p_Phi, p_U, bp, out,
                                          512, 512,
                                          (size_t)1024 * 512, (size_t)512 * 1024,
                                          (size_t)1024 * 1024);
    k_ln<<<M, 256>>>(out, gamma, beta);
}

// round 7
// speedup vs baseline: 1.9947x; 1.3255x over previous
#include <cuda_runtime.h>
#include <cuda_bf16.h>
#include <cstdint>

#define EMBED 1024
#define HEADS 16
#define HDIM  64
#define LSEQ  1024
#define MAXB  4
#define MCH   32
#define OUTD  1024

// ================= helpers =================
__device__ __forceinline__ float frcp(float x) {
    float r; asm("rcp.approx.f32 %0, %1;" : "=f"(r) : "f"(x)); return r;
}

// mma.sync m16n8k16 bf16 -> f32 (row.col): D += A*B
__device__ __forceinline__ void mma16816(float* c, const unsigned* a, const unsigned* b) {
    asm volatile(
        "mma.sync.aligned.m16n8k16.row.col.f32.bf16.bf16.f32 "
        "{%0,%1,%2,%3}, {%4,%5,%6,%7}, {%8,%9}, {%0,%1,%2,%3};"
        : "+f"(c[0]), "+f"(c[1]), "+f"(c[2]), "+f"(c[3])
        : "r"(a[0]), "r"(a[1]), "r"(a[2]), "r"(a[3]), "r"(b[0]), "r"(b[1]));
}

// ================= scratch =================
__device__ float g_WqE[EMBED * HEADS];
__device__ float g_WkE[EMBED * HEADS];
__device__ float g_bqE[HEADS];
__device__ float g_SQ[MAXB * HEADS * LSEQ];
__device__ float g_SK[MAXB * HEADS * LSEQ];
__device__ unsigned g_skmax_bits;
__device__ float g_ynodes[MCH];
__device__ float g_wbar[MCH];
__device__ float g_S[MAXB * HEADS * MCH];
__device__ float g_P[(size_t)MAXB * 512 * EMBED];
__device__ float g_T[(size_t)MAXB * HEADS * MCH * HDIM];
__device__ float g_U[(size_t)MAXB * 512 * OUTD];

__device__ __align__(16) __nv_bfloat16 g_Psih[(size_t)MAXB * 512 * LSEQ];
__device__ __align__(16) __nv_bfloat16 g_Psil[(size_t)MAXB * 512 * LSEQ];
__device__ __align__(16) __nv_bfloat16 g_VTh[(size_t)MAXB * 1024 * 1024];
__device__ __align__(16) __nv_bfloat16 g_VTl[(size_t)MAXB * 1024 * 1024];
__device__ __align__(16) __nv_bfloat16 g_Phih[(size_t)MAXB * LSEQ * 512];
__device__ __align__(16) __nv_bfloat16 g_Phil[(size_t)MAXB * LSEQ * 512];
__device__ __align__(16) __nv_bfloat16 g_UTh[(size_t)MAXB * 1024 * 512];
__device__ __align__(16) __nv_bfloat16 g_UTl[(size_t)MAXB * 1024 * 512];

// ================= K0: effective weights =================
__global__ void k_weff(const float* __restrict__ Wq, const float* __restrict__ Wk,
                       const float* __restrict__ bq, const float* __restrict__ aw) {
    int t = blockIdx.x * blockDim.x + threadIdx.x;
    if (t == 0) g_skmax_bits = 0u;
    int side = t >> 14;
    int u = t & 16383;
    int e = u >> 4, n = u & 15;
    const float* W = side ? Wk : Wq;
    const float* w = aw + side * HDIM;
    float s = 0.f;
#pragma unroll 8
    for (int d = 0; d < HDIM; d++)
        s += W[(size_t)e * (HEADS * HDIM) + n * HDIM + d] * w[d];
    if (side) g_WkE[e * 16 + n] = s;
    else      g_WqE[e * 16 + n] = s;
    if (!side && e == 0) {
        float sb = 0.f;
#pragma unroll 8
        for (int d = 0; d < HDIM; d++) sb += bq[n * HDIM + d] * w[d];
        g_bqE[n] = sb;
    }
}

// ================= K1: sq/sk =================
__global__ void __launch_bounds__(256) k_sqk(const float* __restrict__ qin,
                                             const float* __restrict__ kin) {
    extern __shared__ float sWE[];
    __shared__ float sred[8];
    int side = blockIdx.y;
    const float* WE = side ? g_WkE : g_WqE;
    int tid = threadIdx.x;
    {
        const float4* src = (const float4*)WE;
        float4* dst = (float4*)sWE;
        for (int t = tid; t < (EMBED * HEADS) / 4; t += 256) dst[t] = src[t];
    }
    __syncthreads();

    int n  = tid & 15;
    int rl = tid >> 4;
    int row = blockIdx.x * 16 + rl;
    const float* xr = (side ? kin : qin) + (size_t)row * EMBED;

    float s0 = 0.f, s1 = 0.f, s2 = 0.f, s3 = 0.f;
#pragma unroll 4
    for (int e = 0; e < EMBED; e += 4) {
        float4 xv = *(const float4*)(xr + e);
        s0 += xv.x * sWE[(e + 0) * 16 + n];
        s1 += xv.y * sWE[(e + 1) * 16 + n];
        s2 += xv.z * sWE[(e + 2) * 16 + n];
        s3 += xv.w * sWE[(e + 3) * 16 + n];
    }
    float s = (s0 + s1) + (s2 + s3);
    if (!side) s += g_bqE[n];
    int b = row >> 10, i = row & 1023;
    float* dst = side ? g_SK : g_SQ;
    dst[((b * HEADS + n) << 10) + i] = s;

    if (side) {
        float a = fabsf(s);
        int lane = tid & 31, wid = tid >> 5;
#pragma unroll
        for (int o = 16; o; o >>= 1) a = fmaxf(a, __shfl_xor_sync(0xffffffffu, a, o));
        if (lane == 0) sred[wid] = a;
        __syncthreads();
        if (tid == 0) {
            float mx = 0.f;
#pragma unroll
            for (int w2 = 0; w2 < 8; w2++) mx = fmaxf(mx, sred[w2]);
            atomicMax(&g_skmax_bits, __float_as_uint(mx));
        }
    }
}

// ================= K1b: Chebyshev nodes =================
__global__ void k_cheb() {
    int m = threadIdx.x;
    float smax = __uint_as_float(g_skmax_bits);
    double Y = (double)smax * 1.0005 + 1e-6;
    double th = (2.0 * m + 1.0) * (3.14159265358979323846 / (2.0 * MCH));
    g_ynodes[m] = (float)(Y * cos(th));
    g_wbar[m]   = (float)(((m & 1) ? -1.0 : 1.0) * sin(th));
}

// ================= K2a: Psi (bf16 hi/lo, [m-row][j]) =================
__global__ void __launch_bounds__(256) k_psimat() {
    __shared__ float sp[256][33];
    __shared__ float yn[MCH], wb[MCH];
    int bn = blockIdx.y;
    int b = bn >> 4, n = bn & 15;
    int j0 = blockIdx.x * 256;
    int tid = threadIdx.x;
    if (tid < MCH) { yn[tid] = g_ynodes[tid]; wb[tid] = g_wbar[tid]; }
    __syncthreads();

    {
        float y = g_SK[(bn << 10) + j0 + tid];
        float t[MCH];
        float den = 0.f;
#pragma unroll
        for (int m = 0; m < MCH; m++) {
            float d = y - yn[m];
            d = (fabsf(d) < 1e-12f) ? 1e-12f : d;
            t[m] = wb[m] * frcp(d);
            den += t[m];
        }
        float ri = frcp(den);
#pragma unroll
        for (int m = 0; m < MCH; m++) sp[tid][m] = t[m] * ri;
    }
    __syncthreads();

    int r  = tid >> 3;
    int cg = (tid & 7) * 32;
    size_t base = (((size_t)b * 512) + n * 32 + r) * LSEQ + j0 + cg;
#pragma unroll
    for (int q = 0; q < 32; q++) {
        float x = sp[cg + q][r];
        __nv_bfloat16 h = __float2bfloat16(x);
        g_Psih[base + q] = h;
        g_Psil[base + q] = __float2bfloat16(x - __bfloat162float(h));
    }
}

// ================= K2b: S =================
__global__ void __launch_bounds__(256) k_S() {
    __shared__ float sp[256 * 33];
    __shared__ float yn[MCH], wb[MCH];
    int bn = blockIdx.x;
    int tid = threadIdx.x;
    if (tid < MCH) { yn[tid] = g_ynodes[tid]; wb[tid] = g_wbar[tid]; }
    __syncthreads();

    float acc[MCH];
#pragma unroll
    for (int m = 0; m < MCH; m++) acc[m] = 0.f;
#pragma unroll
    for (int s = 0; s < 4; s++) {
        float y = g_SK[(bn << 10) + tid + s * 256];
        float t[MCH];
        float den = 0.f;
#pragma unroll
        for (int m = 0; m < MCH; m++) {
            float d = y - yn[m];
            d = (fabsf(d) < 1e-12f) ? 1e-12f : d;
            t[m] = wb[m] * frcp(d);
            den += t[m];
        }
        float ri = frcp(den);
#pragma unroll
        for (int m = 0; m < MCH; m++) acc[m] += t[m] * ri;
    }
#pragma unroll
    for (int m = 0; m < MCH; m++) sp[tid * 33 + m] = acc[m];
    __syncthreads();
    if (tid < MCH) {
        float s = 0.f;
        for (int r = 0; r < 256; r++) s += sp[r * 33 + tid];
        g_S[bn * MCH + tid] = s;
    }
}

// ================= transpose + bf16 split:  in[R][C] fp32 -> out[C][R] hi/lo =======
__global__ void __launch_bounds__(256) k_tsplit(const float* __restrict__ in,
                                                __nv_bfloat16* __restrict__ oh,
                                                __nv_bfloat16* __restrict__ ol,
                                                int R, int C) {
    __shared__ float t[32][33];
    int b = blockIdx.z;
    in += (size_t)b * R * C;
    oh += (size_t)b * R * C;
    ol += (size_t)b * R * C;
    int r0 = blockIdx.y * 32, c0 = blockIdx.x * 32;
    int tx = threadIdx.x & 31, ty = threadIdx.x >> 5;
#pragma unroll
    for (int s = 0; s < 4; s++) {
        int r = ty + s * 8;
        t[r][tx] = in[(size_t)(r0 + r) * C + c0 + tx];
    }
    __syncthreads();
#pragma unroll
    for (int s = 0; s < 4; s++) {
        int c = ty + s * 8;
        float x = t[tx][c];
        __nv_bfloat16 h = __float2bfloat16(x);
        size_t o = (size_t)(c0 + c) * R + r0 + tx;
        oh[o] = h;
        ol[o] = __float2bfloat16(x - __bfloat162float(h));
    }
}

// ================= HMMA bf16-split GEMM ==========================================
// C[M,1024] = (Ah+Al)[M,K] @ (Bh+Bl)^T  (B stored [N][K]); fp32 out, optional bias.
// 128x128 CTA tile, 8 warps of 32x64, BK=64, 3-pass split via mma.sync m16n8k16.
#define BKC 64
#define STRD 72   // padded bf16 row stride in smem
#define MMA_SMEM (4 * 128 * STRD * 2)

template <bool BIAS>
__global__ void __launch_bounds__(256) k_gemm_mma(
    const __nv_bfloat16* __restrict__ Ah, const __nv_bfloat16* __restrict__ Al,
    const __nv_bfloat16* __restrict__ Bh, const __nv_bfloat16* __restrict__ Bl,
    const float* __restrict__ bias, float* __restrict__ C,
    int K, size_t sA, size_t sB, size_t sC)
{
    extern __shared__ __nv_bfloat16 sm[];
    __nv_bfloat16* sAh = sm;
    __nv_bfloat16* sAl = sm + 128 * STRD;
    __nv_bfloat16* sBh = sm + 2 * 128 * STRD;
    __nv_bfloat16* sBl = sm + 3 * 128 * STRD;

    int tid = threadIdx.x, lane = tid & 31, wid = tid >> 5;
    int wm = wid >> 1, wn = wid & 1;           // warp tile (32*wm, 64*wn)
    int m0 = blockIdx.y * 128, n0 = blockIdx.x * 128;

    const __nv_bfloat16* gAh = Ah + blockIdx.z * sA + (size_t)m0 * K;
    const __nv_bfloat16* gAl = Al + blockIdx.z * sA + (size_t)m0 * K;
    const __nv_bfloat16* gBh = Bh + blockIdx.z * sB + (size_t)n0 * K;
    const __nv_bfloat16* gBl = Bl + blockIdx.z * sB + (size_t)n0 * K;
    C += blockIdx.z * sC;

    int g = lane >> 2, tg = lane & 3;

    float acc[2][8][4];
#pragma unroll
    for (int a = 0; a < 2; a++)
#pragma unroll
        for (int b = 0; b < 8; b++)
#pragma unroll
            for (int c = 0; c < 4; c++) acc[a][b][c] = 0.f;

    for (int kt = 0; kt < K; kt += BKC) {
        __syncthreads();
        {
            const __nv_bfloat16* srcs[4] = { gAh + kt, gAl + kt, gBh + kt, gBl + kt };
            __nv_bfloat16* dsts[4] = { sAh, sAl, sBh, sBl };
#pragma unroll
            for (int t = 0; t < 4; t++) {
#pragma unroll
                for (int s = 0; s < 4; s++) {
                    int i = tid + s * 256;
                    int row = i >> 3, ch = i & 7;
                    uint4 v = *(const uint4*)(srcs[t] + (size_t)row * K + ch * 8);
                    *(uint4*)(dsts[t] + row * STRD + ch * 8) = v;
                }
            }
        }
        __syncthreads();

#pragma unroll
        for (int ks = 0; ks < 4; ks++) {
            int k0 = ks * 16 + tg * 2;
            unsigned ah[2][4], al[2][4];
#pragma unroll
            for (int mt = 0; mt < 2; mt++) {
                int rb = wm * 32 + mt * 16 + g;
                ah[mt][0] = *(const unsigned*)(sAh + rb * STRD + k0);
                ah[mt][1] = *(const unsigned*)(sAh + (rb + 8) * STRD + k0);
                ah[mt][2] = *(const unsigned*)(sAh + rb * STRD + k0 + 8);
                ah[mt][3] = *(const unsigned*)(sAh + (rb + 8) * STRD + k0 + 8);
                al[mt][0] = *(const unsigned*)(sAl + rb * STRD + k0);
                al[mt][1] = *(const unsigned*)(sAl + (rb + 8) * STRD + k0);
                al[mt][2] = *(const unsigned*)(sAl + rb * STRD + k0 + 8);
                al[mt][3] = *(const unsigned*)(sAl + (rb + 8) * STRD + k0 + 8);
            }
#pragma unroll
            for (int nt = 0; nt < 8; nt++) {
                int cb = wn * 64 + nt * 8 + g;
                unsigned bh[2], bl[2];
                bh[0] = *(const unsigned*)(sBh + cb * STRD + k0);
                bh[1] = *(const unsigned*)(sBh + cb * STRD + k0 + 8);
                bl[0] = *(const unsigned*)(sBl + cb * STRD + k0);
                bl[1] = *(const unsigned*)(sBl + cb * STRD + k0 + 8);
#pragma unroll
                for (int mt = 0; mt < 2; mt++) {
                    mma16816(acc[mt][nt], ah[mt], bh);
                    mma16816(acc[mt][nt], ah[mt], bl);
                    mma16816(acc[mt][nt], al[mt], bh);
                }
            }
        }
    }

    // epilogue
#pragma unroll
    for (int mt = 0; mt < 2; mt++) {
        int row0 = m0 + wm * 32 + mt * 16 + g;
#pragma unroll
        for (int nt = 0; nt < 8; nt++) {
            int col = n0 + wn * 64 + nt * 8 + tg * 2;
            float2 v0, v1;
            v0.x = acc[mt][nt][0]; v0.y = acc[mt][nt][1];
            v1.x = acc[mt][nt][2]; v1.y = acc[mt][nt][3];
            if (BIAS) {
                float2 bv = *(const float2*)(bias + col);
                v0.x += bv.x; v0.y += bv.y;
                v1.x += bv.x; v1.y += bv.y;
            }
            *(float2*)(C + (size_t)row0 * 1024 + col) = v0;
            *(float2*)(C + (size_t)(row0 + 8) * 1024 + col) = v1;
        }
    }
}

// ================= K4: T[bn][m][d] = P[b][n*32+m][:] @ Wv[:, n*64+d] ==============
__global__ void __launch_bounds__(256) k_T(const float* __restrict__ Wv) {
    __shared__ float sp[32][64];
    __shared__ float sw[64][64];
    int bn = blockIdx.x;
    int b = bn >> 4, n = bn & 15;
    int tid = threadIdx.x;
    int m  = tid >> 3;
    int dq = (tid & 7) * 8;

    const float* P = g_P + ((size_t)b * 512 + n * 32) * EMBED;

    float acc[8];
#pragma unroll
    for (int c = 0; c < 8; c++) acc[c] = 0.f;

    for (int e0 = 0; e0 < EMBED; e0 += 64) {
        __syncthreads();
#pragma unroll
        for (int s = 0; s < 2; s++) {
            int f4 = tid + s * 256;
            int row = f4 >> 4, c4 = (f4 & 15) * 4;
            *(float4*)&sp[row][c4] = *(const float4*)(P + (size_t)row * EMBED + e0 + c4);
        }
#pragma unroll
        for (int s = 0; s < 4; s++) {
            int f4 = tid + s * 256;
            int row = f4 >> 4, c4 = (f4 & 15) * 4;
            *(float4*)&sw[row][c4] = *(const float4*)(Wv + (size_t)(e0 + row) * (HEADS * HDIM) + n * 64 + c4);
        }
        __syncthreads();

#pragma unroll 4
        for (int e = 0; e < 64; e++) {
            float p = sp[m][e];
            float4 w0 = *(const float4*)&sw[e][dq];
            float4 w1 = *(const float4*)&sw[e][dq + 4];
            acc[0] += p * w0.x; acc[1] += p * w0.y;
            acc[2] += p * w0.z; acc[3] += p * w0.w;
            acc[4] += p * w1.x; acc[5] += p * w1.y;
            acc[6] += p * w1.z; acc[7] += p * w1.w;
        }
    }

    float* Tp = g_T + ((size_t)bn * MCH + m) * HDIM + dq;
    float4 o0, o1;
    o0.x = acc[0]; o0.y = acc[1]; o0.z = acc[2]; o0.w = acc[3];
    o1.x = acc[4]; o1.y = acc[5]; o1.z = acc[6]; o1.w = acc[7];
    *(float4*)Tp = o0;
    *(float4*)(Tp + 4) = o1;
}

// ================= K5: U[b][n*32+m][o] = T[bn][m][:] @ Wp[n*64+:, o] ==============
__global__ void __launch_bounds__(256) k_U(const float* __restrict__ Wp) {
    __shared__ float sT[32][64];
    __shared__ float sW[16][256];
    int bn = blockIdx.y;
    int b = bn >> 4, n = bn & 15;
    int c0 = blockIdx.x * 256;
    int tid = threadIdx.x;
    int m = tid >> 3;
    int cq = (tid & 7) * 32;

#pragma unroll
    for (int s = 0; s < 2; s++) {
        int f4 = tid + s * 256;
        int row = f4 >> 4, c4 = (f4 & 15) * 4;
        *(float4*)&sT[row][c4] = *(const float4*)(g_T + (size_t)bn * (MCH * HDIM) + row * HDIM + c4);
    }

    float acc[32];
#pragma unroll
    for (int c = 0; c < 32; c++) acc[c] = 0.f;

    for (int dt = 0; dt < 4; dt++) {
        __syncthreads();
#pragma unroll
        for (int s = 0; s < 4; s++) {
            int f4 = tid + s * 256;
            int row = f4 >> 6, c4 = (f4 & 63) * 4;
            *(float4*)&sW[row][c4] =
                *(const float4*)(Wp + (size_t)(n * 64 + dt * 16 + row) * OUTD + c0 + c4);
        }
        __syncthreads();

#pragma unroll
        for (int d = 0; d < 16; d++) {
            float t = sT[m][dt * 16 + d];
#pragma unroll
            for (int q = 0; q < 8; q++) {
                float4 w = *(const float4*)&sW[d][cq + q * 4];
                acc[q * 4 + 0] += t * w.x;
                acc[q * 4 + 1] += t * w.y;
                acc[q * 4 + 2] += t * w.z;
                acc[q * 4 + 3] += t * w.w;
            }
        }
    }

    float* Up = g_U + (((size_t)b * 512) + n * 32 + m) * OUTD + c0 + cq;
#pragma unroll
    for (int q = 0; q < 8; q++) {
        float4 o;
        o.x = acc[q * 4 + 0]; o.y = acc[q * 4 + 1];
        o.z = acc[q * 4 + 2]; o.w = acc[q * 4 + 3];
        *(float4*)(Up + q * 4) = o;
    }
}

// ================= K6: Phi~ (bf16 hi/lo, [i][nm]) =================
__global__ void __launch_bounds__(256) k_phiq() {
    __shared__ float syn[MCH];
    __shared__ float sS[16][MCH];
    int b = blockIdx.y;
    int tid = threadIdx.x;
    int n = tid & 15;
    int ir = tid >> 4;
    int i = blockIdx.x * 16 + ir;

    if (tid < MCH) syn[tid] = g_ynodes[tid];
    for (int t = tid; t < 16 * MCH; t += 256)
        sS[t >> 5][t & 31] = g_S[(b * 16 + (t >> 5)) * MCH + (t & 31)];
    __syncthreads();

    float sq = g_SQ[((b * 16 + n) << 10) + i];
    float phi[MCH];
    float den = 0.f;
#pragma unroll
    for (int m = 0; m < MCH; m++) {
        float u = __expf(2.f * (sq + syn[m]));
        float t = (u - 1.f) * frcp(u + 1.f);
        float p = __expf(t);
        phi[m] = p;
        den += p * sS[n][m];
    }
    float inv = frcp(den);

    size_t base = ((((size_t)b << 10) + i) * 512) + n * 32;
#pragma unroll
    for (int m = 0; m < MCH; m++) {
        float x = phi[m] * inv;
        __nv_bfloat16 h = __float2bfloat16(x);
        g_Phih[base + m] = h;
        g_Phil[base + m] = __float2bfloat16(x - __bfloat162float(h));
    }
}

// ================= K7: layernorm =================
__global__ void __launch_bounds__(256) k_ln(float* __restrict__ y,
                                            const float* __restrict__ gamma,
                                            const float* __restrict__ beta) {
    int row = blockIdx.x, tid = threadIdx.x;
    float4* yp = (float4*)(y + (size_t)row * 1024);
    float4 v = yp[tid];
    float s  = v.x + v.y + v.z + v.w;
    float ss = v.x * v.x + v.y * v.y + v.z * v.z + v.w * v.w;

    __shared__ float red[16];
    int lane = tid & 31, wid = tid >> 5;
#pragma unroll
    for (int o = 16; o; o >>= 1) {
        s  += __shfl_xor_sync(0xffffffffu, s,  o);
        ss += __shfl_xor_sync(0xffffffffu, ss, o);
    }
    if (lane == 0) { red[wid] = s; red[wid + 8] = ss; }
    __syncthreads();
    if (tid == 0) {
        float S = 0.f, SS = 0.f;
        for (int w = 0; w < 8; w++) { S += red[w]; SS += red[w + 8]; }
        red[0] = S; red[1] = SS;
    }
    __syncthreads();
    float mean = red[0] * (1.0f / 1024.0f);
    float var  = red[1] * (1.0f / 1024.0f) - mean * mean;
    float rr = rsqrtf(var + 1e-6f);

    float4 g  = ((const float4*)gamma)[tid];
    float4 bb = ((const float4*)beta)[tid];
    float4 o;
    o.x = (v.x - mean) * rr * g.x + bb.x;
    o.y = (v.y - mean) * rr * g.y + bb.y;
    o.z = (v.z - mean) * rr * g.z + bb.z;
    o.w = (v.w - mean) * rr * g.w + bb.w;
    yp[tid] = o;
}

// ================= launcher =================
extern "C" void kernel_launch(void* const* d_in, const int* in_sizes, int n_in,
                              void* d_out, int out_size) {
    (void)n_in; (void)out_size;
    const float* k_in  = (const float*)d_in[0];
    const float* q_in  = (const float*)d_in[1];
    const float* v_in  = (const float*)d_in[2];
    const float* Wq    = (const float*)d_in[3];
    const float* bq    = (const float*)d_in[4];
    const float* Wk    = (const float*)d_in[5];
    const float* Wv    = (const float*)d_in[6];
    const float* Wp    = (const float*)d_in[7];
    const float* bp    = (const float*)d_in[8];
    const float* aw    = (const float*)d_in[9];
    const float* gamma = (const float*)d_in[10];
    const float* beta  = (const float*)d_in[11];
    float* out = (float*)d_out;

    int B = in_sizes[0] / (LSEQ * EMBED);   // 4
    int M = B * LSEQ;                        // 4096

    float *p_P = nullptr, *p_U = nullptr;
    __nv_bfloat16 *p_Psih, *p_Psil, *p_VTh, *p_VTl, *p_Phih, *p_Phil, *p_UTh, *p_UTl;
    cudaGetSymbolAddress((void**)&p_P,    g_P);
    cudaGetSymbolAddress((void**)&p_U,    g_U);
    cudaGetSymbolAddress((void**)&p_Psih, g_Psih);
    cudaGetSymbolAddress((void**)&p_Psil, g_Psil);
    cudaGetSymbolAddress((void**)&p_VTh,  g_VTh);
    cudaGetSymbolAddress((void**)&p_VTl,  g_VTl);
    cudaGetSymbolAddress((void**)&p_Phih, g_Phih);
    cudaGetSymbolAddress((void**)&p_Phil, g_Phil);
    cudaGetSymbolAddress((void**)&p_UTh,  g_UTh);
    cudaGetSymbolAddress((void**)&p_UTl,  g_UTl);

    cudaFuncSetAttribute(k_sqk, cudaFuncAttributeMaxDynamicSharedMemorySize, 65536);
    cudaFuncSetAttribute(k_gemm_mma<false>, cudaFuncAttributeMaxDynamicSharedMemorySize, MMA_SMEM);
    cudaFuncSetAttribute(k_gemm_mma<true>,  cudaFuncAttributeMaxDynamicSharedMemorySize, MMA_SMEM);

    // V^T split depends only on input v — start first
    k_tsplit<<<dim3(32, 32, B), 256>>>(v_in, p_VTh, p_VTl, 1024, 1024);
    k_weff<<<128, 256>>>(Wq, Wk, bq, aw);
    k_sqk<<<dim3(M / 16, 2), 256, 65536>>>(q_in, k_in);
    k_cheb<<<1, MCH>>>();
    k_psimat<<<dim3(LSEQ / 256, B * HEADS), 256>>>();
    k_S<<<B * HEADS, 256>>>();
    // P[b] (512 x 1024) = Psi_b @ v_b   (HMMA, K = 1024)
    k_gemm_mma<false><<<dim3(8, 4, B), 256, MMA_SMEM>>>(
        p_Psih, p_Psil, p_VTh, p_VTl, nullptr, p_P,
        1024, (size_t)512 * 1024, (size_t)1024 * 1024, (size_t)512 * 1024);
    k_T<<<B * HEADS, 256>>>(Wv);
    k_U<<<dim3(4, B * HEADS), 256>>>(Wp);
    k_tsplit<<<dim3(32, 16, B), 256>>>(p_U, p_UTh, p_UTl, 512, 1024);
    k_phiq<<<dim3(LSEQ / 16, B), 256>>>();
    // out[b] (1024 x 1024) = Phi_b @ U_b + bp   (HMMA, K = 512)
    k_gemm_mma<true><<<dim3(8, 8, B), 256, MMA_SMEM>>>(
        p_Phih, p_Phil, p_UTh, p_UTl, bp, out,
        512, (size_t)1024 * 512, (size_t)1024 * 512, (size_t)1024 * 1024);
    k_ln<<<M, 256>>>(out, gamma, beta);
}

// round 8
// speedup vs baseline: 2.3346x; 1.1704x over previous
#include <cuda_runtime.h>
#include <cuda_bf16.h>
#include <cstdint>

#define EMBED 1024
#define HEADS 16
#define HDIM  64
#define LSEQ  1024
#define MAXB  4
#define MCH   32
#define OUTD  1024
#define PIF   3.14159265358979f

typedef unsigned long long u64;

// ================= helpers =================
__device__ __forceinline__ float frcp(float x) {
    float r; asm("rcp.approx.f32 %0, %1;" : "=f"(r) : "f"(x)); return r;
}
__device__ __forceinline__ u64 fma2(u64 a, u64 b, u64 c) {
    u64 d;
    asm("fma.rn.f32x2 %0, %1, %2, %3;" : "=l"(d) : "l"(a), "l"(b), "l"(c));
    return d;
}
__device__ __forceinline__ uint32_t smem_u32(const void* p) {
    uint32_t a;
    asm("{ .reg .u64 t; cvta.to.shared.u64 t, %1; cvt.u32.u64 %0, t; }" : "=r"(a) : "l"(p));
    return a;
}
__device__ __forceinline__ void mma16816(float* c, const unsigned* a, const unsigned* b) {
    asm volatile(
        "mma.sync.aligned.m16n8k16.row.col.f32.bf16.bf16.f32 "
        "{%0,%1,%2,%3}, {%4,%5,%6,%7}, {%8,%9}, {%0,%1,%2,%3};"
        : "+f"(c[0]), "+f"(c[1]), "+f"(c[2]), "+f"(c[3])
        : "r"(a[0]), "r"(a[1]), "r"(a[2]), "r"(a[3]), "r"(b[0]), "r"(b[1]));
}

// ================= scratch =================
__device__ float g_WqE[EMBED * HEADS];
__device__ float g_WkE[EMBED * HEADS];
__device__ float g_bqE[HEADS];
__device__ float g_SQ[MAXB * HEADS * LSEQ];
__device__ float g_SK[MAXB * HEADS * LSEQ];
__device__ unsigned g_skmax_bits;
__device__ float g_S[MAXB * HEADS * MCH];
__device__ float g_P[(size_t)MAXB * 512 * EMBED];
__device__ float g_T[(size_t)MAXB * HEADS * MCH * HDIM];

__device__ __align__(16) __nv_bfloat16 g_Psih[(size_t)MAXB * 512 * LSEQ];
__device__ __align__(16) __nv_bfloat16 g_Psil[(size_t)MAXB * 512 * LSEQ];
__device__ __align__(16) __nv_bfloat16 g_VTh[(size_t)MAXB * 1024 * 1024];
__device__ __align__(16) __nv_bfloat16 g_VTl[(size_t)MAXB * 1024 * 1024];
__device__ __align__(16) __nv_bfloat16 g_Phih[(size_t)MAXB * LSEQ * 512];
__device__ __align__(16) __nv_bfloat16 g_Phil[(size_t)MAXB * LSEQ * 512];
__device__ __align__(16) __nv_bfloat16 g_UTh[(size_t)MAXB * 1024 * 512];
__device__ __align__(16) __nv_bfloat16 g_UTl[(size_t)MAXB * 1024 * 512];

// ================= K0: effective weights =================
__global__ void k_weff(const float* __restrict__ Wq, const float* __restrict__ Wk,
                       const float* __restrict__ bq, const float* __restrict__ aw) {
    int t = blockIdx.x * blockDim.x + threadIdx.x;
    if (t == 0) g_skmax_bits = 0u;
    int side = t >> 14;
    int u = t & 16383;
    int e = u >> 4, n = u & 15;
    const float* W = side ? Wk : Wq;
    const float* w = aw + side * HDIM;
    float s = 0.f;
#pragma unroll 8
    for (int d = 0; d < HDIM; d++)
        s += W[(size_t)e * (HEADS * HDIM) + n * HDIM + d] * w[d];
    if (side) g_WkE[e * 16 + n] = s;
    else      g_WqE[e * 16 + n] = s;
    if (!side && e == 0) {
        float sb = 0.f;
#pragma unroll 8
        for (int d = 0; d < HDIM; d++) sb += bq[n * HDIM + d] * w[d];
        g_bqE[n] = sb;
    }
}

// ================= K1: sq/sk  (transposed WE, f32x2, conflict-free) ================
// grid (4096/32, 2), 256 threads. Thread: row rl=tid>>3, slice p=tid&7 (e-chunks
// of 4 with chunk ≡ p mod 8), all 16 heads. smem WE^T [16][1028].
#define PADF 1028
#define SQK_SMEM (16 * PADF * 4)
__global__ void __launch_bounds__(256) k_sqk(const float* __restrict__ qin,
                                             const float* __restrict__ kin) {
    extern __shared__ float sWEt[];   // [16][PADF]
    __shared__ float sred[8];
    int side = blockIdx.y;
    const float* WE = side ? g_WkE : g_WqE;
    int tid = threadIdx.x;

    // transpose-load WE[e][n] -> sWEt[n][e]
    for (int idx = tid; idx < EMBED * HEADS; idx += 256) {
        int e = idx >> 4, n = idx & 15;
        sWEt[n * PADF + e] = WE[idx];
    }
    __syncthreads();

    int rl = tid >> 3;                 // 0..31
    int p  = tid & 7;
    int row = blockIdx.x * 32 + rl;
    const float* xr = (side ? kin : qin) + (size_t)row * EMBED;

    u64 acc[16];
#pragma unroll
    for (int n = 0; n < 16; n++) acc[n] = 0ull;

#pragma unroll 4
    for (int i = 0; i < 32; i++) {
        int e = (i * 8 + p) * 4;
        float4 xv = *(const float4*)(xr + e);
        u64 xlo, xhi;
        asm("mov.b64 %0, {%1, %2};" : "=l"(xlo) : "f"(xv.x), "f"(xv.y));
        asm("mov.b64 %0, {%1, %2};" : "=l"(xhi) : "f"(xv.z), "f"(xv.w));
#pragma unroll
        for (int n = 0; n < 16; n++) {
            float4 wv = *(const float4*)&sWEt[n * PADF + e];
            u64 wlo, whi;
            asm("mov.b64 %0, {%1, %2};" : "=l"(wlo) : "f"(wv.x), "f"(wv.y));
            asm("mov.b64 %0, {%1, %2};" : "=l"(whi) : "f"(wv.z), "f"(wv.w));
            acc[n] = fma2(xlo, wlo, acc[n]);
            acc[n] = fma2(xhi, whi, acc[n]);
        }
    }

    // horizontal + butterfly over the 8 p-lanes (lane bits 0..2)
    float s[16];
#pragma unroll
    for (int n = 0; n < 16; n++) {
        float lo, hi;
        asm("mov.b64 {%0, %1}, %2;" : "=f"(lo), "=f"(hi) : "l"(acc[n]));
        s[n] = lo + hi;
    }
#pragma unroll
    for (int msk = 1; msk < 8; msk <<= 1)
#pragma unroll
        for (int n = 0; n < 16; n++)
            s[n] += __shfl_xor_sync(0xffffffffu, s[n], msk);

    int n0 = p * 2;
    float v0 = s[n0], v1 = s[n0 + 1];
    if (!side) { v0 += g_bqE[n0]; v1 += g_bqE[n0 + 1]; }
    int b = row >> 10, ii = row & 1023;
    float* dst = side ? g_SK : g_SQ;
    dst[((b * 16 + n0) << 10) + ii]     = v0;
    dst[((b * 16 + n0 + 1) << 10) + ii] = v1;

    if (side) {
        float a = fmaxf(fabsf(v0), fabsf(v1));
        int lane = tid & 31, wid = tid >> 5;
#pragma unroll
        for (int o = 16; o; o >>= 1) a = fmaxf(a, __shfl_xor_sync(0xffffffffu, a, o));
        if (lane == 0) sred[wid] = a;
        __syncthreads();
        if (tid == 0) {
            float mx = 0.f;
#pragma unroll
            for (int w2 = 0; w2 < 8; w2++) mx = fmaxf(mx, sred[w2]);
            atomicMax(&g_skmax_bits, __float_as_uint(mx));
        }
    }
}

// ---- inline Chebyshev nodes (identical float code in each consumer) ----
#define CHEB_LOCAL(yn, wb, tid) do { \
    if ((tid) < MCH) { \
        float smax = __uint_as_float(g_skmax_bits); \
        float Y = smax * 1.0005f + 1e-6f; \
        float th = (2.f * (tid) + 1.f) * (PIF / 64.f); \
        (yn)[tid] = Y * cosf(th); \
        if (wb) ((float*)(wb))[tid] = (((tid) & 1) ? -sinf(th) : sinf(th)); \
    } \
} while (0)

// ================= K2a: Psi (bf16 hi/lo, [m-row][j]) =================
__global__ void __launch_bounds__(256) k_psimat() {
    __shared__ float sp[256][33];
    __shared__ float yn[MCH], wb[MCH];
    int bn = blockIdx.y;
    int b = bn >> 4, n = bn & 15;
    int j0 = blockIdx.x * 256;
    int tid = threadIdx.x;
    CHEB_LOCAL(yn, wb, tid);
    __syncthreads();

    {
        float y = g_SK[(bn << 10) + j0 + tid];
        float t[MCH];
        float den = 0.f;
#pragma unroll
        for (int m = 0; m < MCH; m++) {
            float d = y - yn[m];
            d = (fabsf(d) < 1e-12f) ? 1e-12f : d;
            t[m] = wb[m] * frcp(d);
            den += t[m];
        }
        float ri = frcp(den);
#pragma unroll
        for (int m = 0; m < MCH; m++) sp[tid][m] = t[m] * ri;
    }
    __syncthreads();

    int r  = tid >> 3;
    int cg = (tid & 7) * 32;
    size_t base = (((size_t)b * 512) + n * 32 + r) * LSEQ + j0 + cg;
#pragma unroll
    for (int q = 0; q < 32; q++) {
        float x = sp[cg + q][r];
        __nv_bfloat16 h = __float2bfloat16(x);
        g_Psih[base + q] = h;
        g_Psil[base + q] = __float2bfloat16(x - __bfloat162float(h));
    }
}

// ================= K2b: S =================
__global__ void __launch_bounds__(256) k_S() {
    __shared__ float sp[256 * 33];
    __shared__ float yn[MCH], wb[MCH];
    int bn = blockIdx.x;
    int tid = threadIdx.x;
    CHEB_LOCAL(yn, wb, tid);
    __syncthreads();

    float acc[MCH];
#pragma unroll
    for (int m = 0; m < MCH; m++) acc[m] = 0.f;
#pragma unroll
    for (int s = 0; s < 4; s++) {
        float y = g_SK[(bn << 10) + tid + s * 256];
        float t[MCH];
        float den = 0.f;
#pragma unroll
        for (int m = 0; m < MCH; m++) {
            float d = y - yn[m];
            d = (fabsf(d) < 1e-12f) ? 1e-12f : d;
            t[m] = wb[m] * frcp(d);
            den += t[m];
        }
        float ri = frcp(den);
#pragma unroll
        for (int m = 0; m < MCH; m++) acc[m] += t[m] * ri;
    }
#pragma unroll
    for (int m = 0; m < MCH; m++) sp[tid * 33 + m] = acc[m];
    __syncthreads();
    if (tid < MCH) {
        float s = 0.f;
        for (int r = 0; r < 256; r++) s += sp[r * 33 + tid];
        g_S[bn * MCH + tid] = s;
    }
}

// ================= transpose + bf16 split:  in[R][C] fp32 -> out[C][R] hi/lo =======
__global__ void __launch_bounds__(256) k_tsplit(const float* __restrict__ in,
                                                __nv_bfloat16* __restrict__ oh,
                                                __nv_bfloat16* __restrict__ ol,
                                                int R, int C) {
    __shared__ float t[32][33];
    int b = blockIdx.z;
    in += (size_t)b * R * C;
    oh += (size_t)b * R * C;
    ol += (size_t)b * R * C;
    int r0 = blockIdx.y * 32, c0 = blockIdx.x * 32;
    int tx = threadIdx.x & 31, ty = threadIdx.x >> 5;
#pragma unroll
    for (int s = 0; s < 4; s++) {
        int r = ty + s * 8;
        t[r][tx] = in[(size_t)(r0 + r) * C + c0 + tx];
    }
    __syncthreads();
#pragma unroll
    for (int s = 0; s < 4; s++) {
        int c = ty + s * 8;
        float x = t[tx][c];
        __nv_bfloat16 h = __float2bfloat16(x);
        size_t o = (size_t)(c0 + c) * R + r0 + tx;
        oh[o] = h;
        ol[o] = __float2bfloat16(x - __bfloat162float(h));
    }
}

// ================= HMMA bf16-split GEMM, cp.async double-buffered ==================
#define BKC 64
#define STRD 72
#define STAGE_ELE (4 * 128 * STRD)
#define MMA_SMEM (2 * STAGE_ELE * 2)

template <bool BIAS>
__global__ void __launch_bounds__(256) k_gemm_mma(
    const __nv_bfloat16* __restrict__ Ah, const __nv_bfloat16* __restrict__ Al,
    const __nv_bfloat16* __restrict__ Bh, const __nv_bfloat16* __restrict__ Bl,
    const float* __restrict__ bias, float* __restrict__ C,
    int K, size_t sA, size_t sB, size_t sC)
{
    extern __shared__ __nv_bfloat16 sm[];
    uint32_t sbase = smem_u32(sm);

    int tid = threadIdx.x, lane = tid & 31, wid = tid >> 5;
    int wm = wid >> 1, wn = wid & 1;
    int m0 = blockIdx.y * 128, n0 = blockIdx.x * 128;

    const __nv_bfloat16* srcs[4] = {
        Ah + blockIdx.z * sA + (size_t)m0 * K,
        Al + blockIdx.z * sA + (size_t)m0 * K,
        Bh + blockIdx.z * sB + (size_t)n0 * K,
        Bl + blockIdx.z * sB + (size_t)n0 * K };
    C += blockIdx.z * sC;

    int g = lane >> 2, tg = lane & 3;
    const int nch = K >> 6;

    float acc[2][8][4];
#pragma unroll
    for (int a = 0; a < 2; a++)
#pragma unroll
        for (int b = 0; b < 8; b++)
#pragma unroll
            for (int c = 0; c < 4; c++) acc[a][b][c] = 0.f;

    // stage loader: 4 tiles x (128 rows x 64 bf16) via cp.async 16B
    auto load_stage = [&](int st, int c) {
#pragma unroll
        for (int t = 0; t < 4; t++) {
#pragma unroll
            for (int s = 0; s < 4; s++) {
                int i = tid + s * 256;
                int row = i >> 3, ch = (i & 7) * 8;
                const void* gp = srcs[t] + (size_t)row * K + c * BKC + ch;
                uint32_t dp = sbase + (uint32_t)(st * STAGE_ELE + t * 128 * STRD + row * STRD + ch) * 2;
                asm volatile("cp.async.cg.shared.global [%0], [%1], 16;" :: "r"(dp), "l"(gp));
            }
        }
        asm volatile("cp.async.commit_group;");
    };

    load_stage(0, 0);

    for (int c = 0; c < nch; c++) {
        if (c + 1 < nch) {
            load_stage((c + 1) & 1, c + 1);
            asm volatile("cp.async.wait_group 1;");
        } else {
            asm volatile("cp.async.wait_group 0;");
        }
        __syncthreads();

        const __nv_bfloat16* sAh = sm + (size_t)(c & 1) * STAGE_ELE;
        const __nv_bfloat16* sAl = sAh + 128 * STRD;
        const __nv_bfloat16* sBh = sAh + 2 * 128 * STRD;
        const __nv_bfloat16* sBl = sAh + 3 * 128 * STRD;

#pragma unroll
        for (int ks = 0; ks < 4; ks++) {
            int k0 = ks * 16 + tg * 2;
            unsigned ah[2][4], al[2][4];
#pragma unroll
            for (int mt = 0; mt < 2; mt++) {
                int rb = wm * 32 + mt * 16 + g;
                ah[mt][0] = *(const unsigned*)(sAh + rb * STRD + k0);
                ah[mt][1] = *(const unsigned*)(sAh + (rb + 8) * STRD + k0);
                ah[mt][2] = *(const unsigned*)(sAh + rb * STRD + k0 + 8);
                ah[mt][3] = *(const unsigned*)(sAh + (rb + 8) * STRD + k0 + 8);
                al[mt][0] = *(const unsigned*)(sAl + rb * STRD + k0);
                al[mt][1] = *(const unsigned*)(sAl + (rb + 8) * STRD + k0);
                al[mt][2] = *(const unsigned*)(sAl + rb * STRD + k0 + 8);
                al[mt][3] = *(const unsigned*)(sAl + (rb + 8) * STRD + k0 + 8);
            }
#pragma unroll
            for (int nt = 0; nt < 8; nt++) {
                int cb = wn * 64 + nt * 8 + g;
                unsigned bh[2], bl[2];
                bh[0] = *(const unsigned*)(sBh + cb * STRD + k0);
                bh[1] = *(const unsigned*)(sBh + cb * STRD + k0 + 8);
                bl[0] = *(const unsigned*)(sBl + cb * STRD + k0);
                bl[1] = *(const unsigned*)(sBl + cb * STRD + k0 + 8);
#pragma unroll
                for (int mt = 0; mt < 2; mt++) {
                    mma16816(acc[mt][nt], ah[mt], bh);
                    mma16816(acc[mt][nt], ah[mt], bl);
                    mma16816(acc[mt][nt], al[mt], bh);
                }
            }
        }
        __syncthreads();
    }

#pragma unroll
    for (int mt = 0; mt < 2; mt++) {
        int row0 = m0 + wm * 32 + mt * 16 + g;
#pragma unroll
        for (int nt = 0; nt < 8; nt++) {
            int col = n0 + wn * 64 + nt * 8 + tg * 2;
            float2 v0, v1;
            v0.x = acc[mt][nt][0]; v0.y = acc[mt][nt][1];
            v1.x = acc[mt][nt][2]; v1.y = acc[mt][nt][3];
            if (BIAS) {
                float2 bv = *(const float2*)(bias + col);
                v0.x += bv.x; v0.y += bv.y;
                v1.x += bv.x; v1.y += bv.y;
            }
            *(float2*)(C + (size_t)row0 * 1024 + col) = v0;
            *(float2*)(C + (size_t)(row0 + 8) * 1024 + col) = v1;
        }
    }
}

// ================= K4: T[bn][m][d] = P[b][n*32+m][:] @ Wv[:, n*64+d] ==============
__global__ void __launch_bounds__(256) k_T(const float* __restrict__ Wv) {
    __shared__ float sp[32][64];
    __shared__ float sw[64][64];
    int bn = blockIdx.x;
    int b = bn >> 4, n = bn & 15;
    int tid = threadIdx.x;
    int m  = tid >> 3;
    int dq = (tid & 7) * 8;

    const float* P = g_P + ((size_t)b * 512 + n * 32) * EMBED;

    float acc[8];
#pragma unroll
    for (int c = 0; c < 8; c++) acc[c] = 0.f;

    for (int e0 = 0; e0 < EMBED; e0 += 64) {
        __syncthreads();
#pragma unroll
        for (int s = 0; s < 2; s++) {
            int f4 = tid + s * 256;
            int row = f4 >> 4, c4 = (f4 & 15) * 4;
            *(float4*)&sp[row][c4] = *(const float4*)(P + (size_t)row * EMBED + e0 + c4);
        }
#pragma unroll
        for (int s = 0; s < 4; s++) {
            int f4 = tid + s * 256;
            int row = f4 >> 4, c4 = (f4 & 15) * 4;
            *(float4*)&sw[row][c4] = *(const float4*)(Wv + (size_t)(e0 + row) * (HEADS * HDIM) + n * 64 + c4);
        }
        __syncthreads();

#pragma unroll 4
        for (int e = 0; e < 64; e++) {
            float p = sp[m][e];
            float4 w0 = *(const float4*)&sw[e][dq];
            float4 w1 = *(const float4*)&sw[e][dq + 4];
            acc[0] += p * w0.x; acc[1] += p * w0.y;
            acc[2] += p * w0.z; acc[3] += p * w0.w;
            acc[4] += p * w1.x; acc[5] += p * w1.y;
            acc[6] += p * w1.z; acc[7] += p * w1.w;
        }
    }

    float* Tp = g_T + ((size_t)bn * MCH + m) * HDIM + dq;
    float4 o0, o1;
    o0.x = acc[0]; o0.y = acc[1]; o0.z = acc[2]; o0.w = acc[3];
    o1.x = acc[4]; o1.y = acc[5]; o1.z = acc[6]; o1.w = acc[7];
    *(float4*)Tp = o0;
    *(float4*)(Tp + 4) = o1;
}

// ================= K5: U + fused transpose/bf16 split -> UT[o][nm] ================
// grid (4 ochunks, 64 bn), 256 threads, dynamic smem
#define KU_SMEM ((2048 + 4096 + 32 * 264) * 4)
__global__ void __launch_bounds__(256) k_U(const float* __restrict__ Wp) {
    extern __shared__ float us[];
    float* sT = us;                 // [32][64]
    float* sW = us + 2048;          // [16][256]
    float* sO = us + 2048 + 4096;   // [32][264]

    int bn = blockIdx.y;
    int b = bn >> 4, n = bn & 15;
    int c0 = blockIdx.x * 256;
    int tid = threadIdx.x;
    int m = tid >> 3;
    int cq = (tid & 7) * 32;

#pragma unroll
    for (int s = 0; s < 2; s++) {
        int f4 = tid + s * 256;
        int row = f4 >> 4, c4 = (f4 & 15) * 4;
        *(float4*)&sT[row * 64 + c4] = *(const float4*)(g_T + (size_t)bn * (MCH * HDIM) + row * HDIM + c4);
    }

    float acc[32];
#pragma unroll
    for (int c = 0; c < 32; c++) acc[c] = 0.f;

    for (int dt = 0; dt < 4; dt++) {
        __syncthreads();
#pragma unroll
        for (int s = 0; s < 4; s++) {
            int f4 = tid + s * 256;
            int row = f4 >> 6, c4 = (f4 & 63) * 4;
            *(float4*)&sW[row * 256 + c4] =
                *(const float4*)(Wp + (size_t)(n * 64 + dt * 16 + row) * OUTD + c0 + c4);
        }
        __syncthreads();

#pragma unroll
        for (int d = 0; d < 16; d++) {
            float t = sT[m * 64 + dt * 16 + d];
#pragma unroll
            for (int q = 0; q < 8; q++) {
                float4 w = *(const float4*)&sW[d * 256 + cq + q * 4];
                acc[q * 4 + 0] += t * w.x;
                acc[q * 4 + 1] += t * w.y;
                acc[q * 4 + 2] += t * w.z;
                acc[q * 4 + 3] += t * w.w;
            }
        }
    }

    // stage to smem, then transposed bf16 hi/lo write (coalesced 64B rows)
#pragma unroll
    for (int q = 0; q < 8; q++) {
        float4 o;
        o.x = acc[q * 4 + 0]; o.y = acc[q * 4 + 1];
        o.z = acc[q * 4 + 2]; o.w = acc[q * 4 + 3];
        *(float4*)&sO[m * 264 + cq + q * 4] = o;
    }
    __syncthreads();

    {
        int o = c0 + tid;
        size_t rowbase = (((size_t)b * 1024) + o) * 512 + n * 32;
        unsigned hh[16], ll[16];
#pragma unroll
        for (int mm = 0; mm < 16; mm++) {
            float x0 = sO[(2 * mm) * 264 + tid];
            float x1 = sO[(2 * mm + 1) * 264 + tid];
            __nv_bfloat16 h0 = __float2bfloat16(x0);
            __nv_bfloat16 h1 = __float2bfloat16(x1);
            __nv_bfloat16 l0 = __float2bfloat16(x0 - __bfloat162float(h0));
            __nv_bfloat16 l1 = __float2bfloat16(x1 - __bfloat162float(h1));
            __nv_bfloat162 hp; hp.x = h0; hp.y = h1;
            __nv_bfloat162 lp; lp.x = l0; lp.y = l1;
            hh[mm] = *(unsigned*)&hp;
            ll[mm] = *(unsigned*)&lp;
        }
#pragma unroll
        for (int q = 0; q < 4; q++) {
            *(uint4*)(g_UTh + rowbase + q * 8) = *(uint4*)&hh[q * 4];
            *(uint4*)(g_UTl + rowbase + q * 8) = *(uint4*)&ll[q * 4];
        }
    }
}

// ================= K6: Phi~ (bf16 hi/lo, [i][nm]) =================
__global__ void __launch_bounds__(256) k_phiq() {
    __shared__ float syn[MCH];
    __shared__ float sS[16][MCH];
    int b = blockIdx.y;
    int tid = threadIdx.x;
    int n = tid & 15;
    int ir = tid >> 4;
    int i = blockIdx.x * 16 + ir;

    CHEB_LOCAL(syn, (float*)0, tid);
    for (int t = tid; t < 16 * MCH; t += 256)
        sS[t >> 5][t & 31] = g_S[(b * 16 + (t >> 5)) * MCH + (t & 31)];
    __syncthreads();

    float sq = g_SQ[((b * 16 + n) << 10) + i];
    float phi[MCH];
    float den = 0.f;
#pragma unroll
    for (int m = 0; m < MCH; m++) {
        float u = __expf(2.f * (sq + syn[m]));
        float t = (u - 1.f) * frcp(u + 1.f);
        float p = __expf(t);
        phi[m] = p;
        den += p * sS[n][m];
    }
    float inv = frcp(den);

    size_t base = ((((size_t)b << 10) + i) * 512) + n * 32;
#pragma unroll
    for (int m = 0; m < MCH; m++) {
        float x = phi[m] * inv;
        __nv_bfloat16 h = __float2bfloat16(x);
        g_Phih[base + m] = h;
        g_Phil[base + m] = __float2bfloat16(x - __bfloat162float(h));
    }
}

// ================= K7: layernorm =================
__global__ void __launch_bounds__(256) k_ln(float* __restrict__ y,
                                            const float* __restrict__ gamma,
                                            const float* __restrict__ beta) {
    int row = blockIdx.x, tid = threadIdx.x;
    float4* yp = (float4*)(y + (size_t)row * 1024);
    float4 v = yp[tid];
    float s  = v.x + v.y + v.z + v.w;
    float ss = v.x * v.x + v.y * v.y + v.z * v.z + v.w * v.w;

    __shared__ float red[16];
    int lane = tid & 31, wid = tid >> 5;
#pragma unroll
    for (int o = 16; o; o >>= 1) {
        s  += __shfl_xor_sync(0xffffffffu, s,  o);
        ss += __shfl_xor_sync(0xffffffffu, ss, o);
    }
    if (lane == 0) { red[wid] = s; red[wid + 8] = ss; }
    __syncthreads();
    if (tid == 0) {
        float S = 0.f, SS = 0.f;
        for (int w = 0; w < 8; w++) { S += red[w]; SS += red[w + 8]; }
        red[0] = S; red[1] = SS;
    }
    __syncthreads();
    float mean = red[0] * (1.0f / 1024.0f);
    float var  = red[1] * (1.0f / 1024.0f) - mean * mean;
    float rr = rsqrtf(var + 1e-6f);

    float4 g  = ((const float4*)gamma)[tid];
    float4 bb = ((const float4*)beta)[tid];
    float4 o;
    o.x = (v.x - mean) * rr * g.x + bb.x;
    o.y = (v.y - mean) * rr * g.y + bb.y;
    o.z = (v.z - mean) * rr * g.z + bb.z;
    o.w = (v.w - mean) * rr * g.w + bb.w;
    yp[tid] = o;
}

// ================= launcher =================
extern "C" void kernel_launch(void* const* d_in, const int* in_sizes, int n_in,
                              void* d_out, int out_size) {
    (void)n_in; (void)out_size;
    const float* k_in  = (const float*)d_in[0];
    const float* q_in  = (const float*)d_in[1];
    const float* v_in  = (const float*)d_in[2];
    const float* Wq    = (const float*)d_in[3];
    const float* bq    = (const float*)d_in[4];
    const float* Wk    = (const float*)d_in[5];
    const float* Wv    = (const float*)d_in[6];
    const float* Wp    = (const float*)d_in[7];
    const float* bp    = (const float*)d_in[8];
    const float* aw    = (const float*)d_in[9];
    const float* gamma = (const float*)d_in[10];
    const float* beta  = (const float*)d_in[11];
    float* out = (float*)d_out;

    int B = in_sizes[0] / (LSEQ * EMBED);   // 4
    int M = B * LSEQ;                        // 4096

    float* p_P = nullptr;
    __nv_bfloat16 *p_Psih, *p_Psil, *p_VTh, *p_VTl, *p_Phih, *p_Phil, *p_UTh, *p_UTl;
    cudaGetSymbolAddress((void**)&p_P,    g_P);
    cudaGetSymbolAddress((void**)&p_Psih, g_Psih);
    cudaGetSymbolAddress((void**)&p_Psil, g_Psil);
    cudaGetSymbolAddress((void**)&p_VTh,  g_VTh);
    cudaGetSymbolAddress((void**)&p_VTl,  g_VTl);
    cudaGetSymbolAddress((void**)&p_Phih, g_Phih);
    cudaGetSymbolAddress((void**)&p_Phil, g_Phil);
    cudaGetSymbolAddress((void**)&p_UTh,  g_UTh);
    cudaGetSymbolAddress((void**)&p_UTl,  g_UTl);

    cudaFuncSetAttribute(k_sqk, cudaFuncAttributeMaxDynamicSharedMemorySize, SQK_SMEM);
    cudaFuncSetAttribute(k_U,   cudaFuncAttributeMaxDynamicSharedMemorySize, KU_SMEM);
    cudaFuncSetAttribute(k_gemm_mma<false>, cudaFuncAttributeMaxDynamicSharedMemorySize, MMA_SMEM);
    cudaFuncSetAttribute(k_gemm_mma<true>,  cudaFuncAttributeMaxDynamicSharedMemorySize, MMA_SMEM);

    k_tsplit<<<dim3(32, 32, B), 256>>>(v_in, p_VTh, p_VTl, 1024, 1024);
    k_weff<<<128, 256>>>(Wq, Wk, bq, aw);
    k_sqk<<<dim3(M / 32, 2), 256, SQK_SMEM>>>(q_in, k_in);
    k_psimat<<<dim3(LSEQ / 256, B * HEADS), 256>>>();
    k_S<<<B * HEADS, 256>>>();
    // P[b] (512 x 1024) = Psi_b @ v_b   (HMMA, K = 1024)
    k_gemm_mma<false><<<dim3(8, 4, B), 256, MMA_SMEM>>>(
        p_Psih, p_Psil, p_VTh, p_VTl, nullptr, p_P,
        1024, (size_t)512 * 1024, (size_t)1024 * 1024, (size_t)512 * 1024);
    k_T<<<B * HEADS, 256>>>(Wv);
    k_U<<<dim3(4, B * HEADS), 256, KU_SMEM>>>(Wp);
    k_phiq<<<dim3(LSEQ / 16, B), 256>>>();
    // out[b] (1024 x 1024) = Phi_b @ U_b + bp   (HMMA, K = 512)
    k_gemm_mma<true><<<dim3(8, 8, B), 256, MMA_SMEM>>>(
        p_Phih, p_Phil, p_UTh, p_UTl, bp, out,
        512, (size_t)1024 * 512, (size_t)1024 * 512, (size_t)1024 * 1024);
    k_ln<<<M, 256>>>(out, gamma, beta);
}